// round 2
// baseline (speedup 1.0000x reference)
#include <cuda_runtime.h>
#include <math.h>

// Problem constants
constexpr int Bc = 4, Tc = 4096, Dc = 1024, Hc = 16, HDc = 64;
constexpr int BT = Bc * Tc;          // 16384 rows
constexpr int BH = Bc * Hc;          // 64 (b,h) pairs
constexpr int SPLIT = 8;             // T-split for kv reduction

// Scratch (device globals: no allocation allowed in kernel_launch)
__device__ float g_q[BT * Dc];
__device__ float g_k[BT * Dc];
__device__ float g_v[BT * Dc];
__device__ float g_attn[BT * Dc];
__device__ float g_kvp[BH * SPLIT * HDc * HDc];
__device__ float g_ksp[BH * SPLIT * HDc];
__device__ float g_kv[BH * HDc * HDc];
__device__ float g_ksum[BH * HDc];
__device__ unsigned char g_mask[BT];

__device__ __forceinline__ float phi(float x) {
    // elu(x)+1 : x>0 -> x+1 ; x<=0 -> exp(x)
    return x > 0.f ? x + 1.f : expf(x);
}

// ---------------------------------------------------------------------------
// Normalize mask of unknown dtype (bool/int8, int32, float32) to uint8 0/1.
// Detection scans first 4096 raw bytes:
//   byte 0x3F present           -> float32 (high byte of 1.0f)
//   nonzero byte at pos%4 != 0  -> bool/int8
//   else                        -> int32
// grid 64 x 256
// ---------------------------------------------------------------------------
__global__ __launch_bounds__(256) void mask_convert_kernel(const unsigned char* __restrict__ mraw)
{
    __shared__ int s_float, s_odd;
    if (threadIdx.x == 0) { s_float = 0; s_odd = 0; }
    __syncthreads();
    for (int i = threadIdx.x; i < 4096; i += 256) {
        unsigned char v = mraw[i];
        if (v == 0x3F) s_float = 1;
        if (v != 0 && (i & 3) != 0) s_odd = 1;
    }
    __syncthreads();
    const int dtype = s_float ? 2 : (s_odd ? 0 : 1);  // 0=bool/int8, 1=int32, 2=float32

    const int m0 = blockIdx.x * 256 + threadIdx.x;
    for (int m = m0; m < BT; m += 64 * 256) {
        unsigned char r;
        if (dtype == 0)      r = (mraw[m] != 0);
        else if (dtype == 1) r = (((const int*)mraw)[m] != 0);
        else                 r = (((const float*)mraw)[m] != 0.0f);
        g_mask[m] = r;
    }
}

// ---------------------------------------------------------------------------
// GEMM: C[M,N] = A[M,K] @ W[N,K]^T  (both row-major), M=16384, N=K=1024
// op: 0 = none, 1 = phi (Q), 2 = phi + mask-zero (K), 3 = mask-zero (V)
// mask[m] (m = b*T + t) nonzero -> zero the row (for op>=2)
// ---------------------------------------------------------------------------
__global__ __launch_bounds__(256) void gemm_nt_kernel(
    const float* __restrict__ A, const float* __restrict__ W,
    float* __restrict__ C, const unsigned char* __restrict__ mask, int op)
{
    constexpr int K = Dc, N = Dc;
    __shared__ __align__(16) float As[16][132];  // [k][m], padded
    __shared__ __align__(16) float Bs[16][132];  // [k][n], padded

    const int tid = threadIdx.x;
    const int brow = blockIdx.y, bcol = blockIdx.x;
    const float* Ap = A + (size_t)brow * 128 * K;
    const float* Wp = W + (size_t)bcol * 128 * K;

    float acc[8][8];
#pragma unroll
    for (int i = 0; i < 8; i++)
#pragma unroll
        for (int j = 0; j < 8; j++) acc[i][j] = 0.f;

    const int tm = (tid >> 4) * 8;
    const int tn = (tid & 15) * 8;

    for (int k0 = 0; k0 < K; k0 += 16) {
#pragma unroll
        for (int it = 0; it < 2; it++) {
            int i = tid + it * 256;           // 0..511 float4 slots
            int r = i >> 2;                   // row 0..127
            int c4 = (i & 3) * 4;             // k-offset 0,4,8,12
            float4 av = *(const float4*)(Ap + (size_t)r * K + k0 + c4);
            As[c4 + 0][r] = av.x; As[c4 + 1][r] = av.y;
            As[c4 + 2][r] = av.z; As[c4 + 3][r] = av.w;
            float4 wv = *(const float4*)(Wp + (size_t)r * K + k0 + c4);
            Bs[c4 + 0][r] = wv.x; Bs[c4 + 1][r] = wv.y;
            Bs[c4 + 2][r] = wv.z; Bs[c4 + 3][r] = wv.w;
        }
        __syncthreads();
#pragma unroll
        for (int kk = 0; kk < 16; kk++) {
            float a[8], bb[8];
            *(float4*)(a)      = *(const float4*)&As[kk][tm];
            *(float4*)(a + 4)  = *(const float4*)&As[kk][tm + 4];
            *(float4*)(bb)     = *(const float4*)&Bs[kk][tn];
            *(float4*)(bb + 4) = *(const float4*)&Bs[kk][tn + 4];
#pragma unroll
            for (int i = 0; i < 8; i++)
#pragma unroll
                for (int j = 0; j < 8; j++)
                    acc[i][j] = fmaf(a[i], bb[j], acc[i][j]);
        }
        __syncthreads();
    }

#pragma unroll
    for (int i = 0; i < 8; i++) {
        int m = brow * 128 + tm + i;
        bool mz = (op >= 2) && (mask[m] != 0);
#pragma unroll
        for (int j = 0; j < 8; j += 4) {
            float4 r;
            r.x = acc[i][j]; r.y = acc[i][j + 1];
            r.z = acc[i][j + 2]; r.w = acc[i][j + 3];
            if (op == 1 || op == 2) {
                r.x = phi(r.x); r.y = phi(r.y); r.z = phi(r.z); r.w = phi(r.w);
            }
            if (mz) { r.x = 0.f; r.y = 0.f; r.z = 0.f; r.w = 0.f; }
            *(float4*)(C + (size_t)m * N + bcol * 128 + tn + j) = r;
        }
    }
}

// ---------------------------------------------------------------------------
// kv partial: for (b,h,split): kv[d][e] += k[t,d]*v[t,e]; ksum[d] += k[t,d]
// grid (BH, SPLIT), 256 threads
// ---------------------------------------------------------------------------
__global__ __launch_bounds__(256) void kv_partial_kernel()
{
    const int tid = threadIdx.x;
    const int bh = blockIdx.x, sy = blockIdx.y;
    const int b = bh >> 4, h = bh & 15;
    const int t0 = sy * (Tc / SPLIT);

    __shared__ __align__(16) float Ks[32][64];
    __shared__ __align__(16) float Vs[32][64];

    float acc[16];
#pragma unroll
    for (int j = 0; j < 16; j++) acc[j] = 0.f;
    float ks = 0.f;

    const int d = tid >> 2;
    const int eb = (tid & 3) * 16;
    const size_t base = ((size_t)b * Tc) * Dc + h * 64;

    for (int tc = 0; tc < Tc / SPLIT; tc += 32) {
#pragma unroll
        for (int it = 0; it < 2; it++) {
            int i = tid + it * 256;           // 0..511 float4 slots
            int tl = i >> 4;                  // 0..31
            int c4 = (i & 15) * 4;            // 0..60
            size_t off = base + (size_t)(t0 + tc + tl) * Dc + c4;
            *(float4*)&Ks[tl][c4] = *(const float4*)(g_k + off);
            *(float4*)&Vs[tl][c4] = *(const float4*)(g_v + off);
        }
        __syncthreads();
#pragma unroll
        for (int t = 0; t < 32; t++) {
            float kd = Ks[t][d];
            ks += kd;  // only (tid&3)==0 lanes store this
            float4 v0 = *(const float4*)&Vs[t][eb];
            float4 v1 = *(const float4*)&Vs[t][eb + 4];
            float4 v2 = *(const float4*)&Vs[t][eb + 8];
            float4 v3 = *(const float4*)&Vs[t][eb + 12];
            acc[0]  = fmaf(kd, v0.x, acc[0]);  acc[1]  = fmaf(kd, v0.y, acc[1]);
            acc[2]  = fmaf(kd, v0.z, acc[2]);  acc[3]  = fmaf(kd, v0.w, acc[3]);
            acc[4]  = fmaf(kd, v1.x, acc[4]);  acc[5]  = fmaf(kd, v1.y, acc[5]);
            acc[6]  = fmaf(kd, v1.z, acc[6]);  acc[7]  = fmaf(kd, v1.w, acc[7]);
            acc[8]  = fmaf(kd, v2.x, acc[8]);  acc[9]  = fmaf(kd, v2.y, acc[9]);
            acc[10] = fmaf(kd, v2.z, acc[10]); acc[11] = fmaf(kd, v2.w, acc[11]);
            acc[12] = fmaf(kd, v3.x, acc[12]); acc[13] = fmaf(kd, v3.y, acc[13]);
            acc[14] = fmaf(kd, v3.z, acc[14]); acc[15] = fmaf(kd, v3.w, acc[15]);
        }
        __syncthreads();
    }

    float* outp = g_kvp + ((size_t)(bh * SPLIT + sy)) * 4096 + d * 64 + eb;
    *(float4*)(outp + 0)  = make_float4(acc[0], acc[1], acc[2], acc[3]);
    *(float4*)(outp + 4)  = make_float4(acc[4], acc[5], acc[6], acc[7]);
    *(float4*)(outp + 8)  = make_float4(acc[8], acc[9], acc[10], acc[11]);
    *(float4*)(outp + 12) = make_float4(acc[12], acc[13], acc[14], acc[15]);
    if ((tid & 3) == 0)
        g_ksp[(bh * SPLIT + sy) * 64 + d] = ks;
}

// ---------------------------------------------------------------------------
// reduce partials across SPLIT. grid BH, 256 threads
// ---------------------------------------------------------------------------
__global__ __launch_bounds__(256) void kv_reduce_kernel()
{
    const int bh = blockIdx.x, tid = threadIdx.x;
#pragma unroll
    for (int j = 0; j < 4; j++) {
        int off = tid * 16 + j * 4;
        float4 s = make_float4(0.f, 0.f, 0.f, 0.f);
#pragma unroll
        for (int sp = 0; sp < SPLIT; sp++) {
            float4 p = *(const float4*)(g_kvp + ((size_t)(bh * SPLIT + sp)) * 4096 + off);
            s.x += p.x; s.y += p.y; s.z += p.z; s.w += p.w;
        }
        *(float4*)(g_kv + (size_t)bh * 4096 + off) = s;
    }
    if (tid < 64) {
        float s = 0.f;
#pragma unroll
        for (int sp = 0; sp < SPLIT; sp++)
            s += g_ksp[(bh * SPLIT + sp) * 64 + tid];
        g_ksum[bh * 64 + tid] = s;
    }
}

// ---------------------------------------------------------------------------
// attn out: out[t,e] = (sum_d q[t,d]*kv[d,e]) / max(q[t]·ksum, 1e-6)
// grid (T/64, BH), 256 threads; 64 t-rows per block, 4 threads per row
// ---------------------------------------------------------------------------
__global__ __launch_bounds__(256) void attn_out_kernel()
{
    const int tid = threadIdx.x;
    const int bh = blockIdx.y;
    const int b = bh >> 4, h = bh & 15;
    const int t0 = blockIdx.x * 64;

    __shared__ __align__(16) float KV[4096];   // [d][e]
    __shared__ float Qs[64][65];               // [d][t_local] padded
    __shared__ float Ksm[64];

#pragma unroll
    for (int j = 0; j < 4; j++) {
        int f = tid + j * 256;                 // float4 slot
        *(float4*)&KV[f * 4] = *(const float4*)(g_kv + (size_t)bh * 4096 + f * 4);
    }
    if (tid < 64) Ksm[tid] = g_ksum[bh * 64 + tid];

    const size_t base = ((size_t)b * Tc) * Dc + h * 64;
#pragma unroll
    for (int j = 0; j < 16; j++) {
        int i = tid + j * 256;
        int tl = i >> 6, d = i & 63;
        Qs[d][tl] = g_q[base + (size_t)(t0 + tl) * Dc + d];
    }
    __syncthreads();

    const int tl = tid >> 2;
    const int eb = (tid & 3) * 16;
    float acc[16];
#pragma unroll
    for (int j = 0; j < 16; j++) acc[j] = 0.f;
    float nrm = 0.f;

#pragma unroll
    for (int d2 = 0; d2 < 64; d2++) {
        float qd = Qs[d2][tl];
        nrm = fmaf(qd, Ksm[d2], nrm);
        const float4* kvp = (const float4*)&KV[d2 * 64 + eb];
        float4 v0 = kvp[0], v1 = kvp[1], v2 = kvp[2], v3 = kvp[3];
        acc[0]  = fmaf(qd, v0.x, acc[0]);  acc[1]  = fmaf(qd, v0.y, acc[1]);
        acc[2]  = fmaf(qd, v0.z, acc[2]);  acc[3]  = fmaf(qd, v0.w, acc[3]);
        acc[4]  = fmaf(qd, v1.x, acc[4]);  acc[5]  = fmaf(qd, v1.y, acc[5]);
        acc[6]  = fmaf(qd, v1.z, acc[6]);  acc[7]  = fmaf(qd, v1.w, acc[7]);
        acc[8]  = fmaf(qd, v2.x, acc[8]);  acc[9]  = fmaf(qd, v2.y, acc[9]);
        acc[10] = fmaf(qd, v2.z, acc[10]); acc[11] = fmaf(qd, v2.w, acc[11]);
        acc[12] = fmaf(qd, v3.x, acc[12]); acc[13] = fmaf(qd, v3.y, acc[13]);
        acc[14] = fmaf(qd, v3.z, acc[14]); acc[15] = fmaf(qd, v3.w, acc[15]);
    }

    float inv = 1.f / fmaxf(nrm, 1e-6f);
    float* op = g_attn + base + (size_t)(t0 + tl) * Dc + eb;
    *(float4*)(op + 0)  = make_float4(acc[0] * inv, acc[1] * inv, acc[2] * inv, acc[3] * inv);
    *(float4*)(op + 4)  = make_float4(acc[4] * inv, acc[5] * inv, acc[6] * inv, acc[7] * inv);
    *(float4*)(op + 8)  = make_float4(acc[8] * inv, acc[9] * inv, acc[10] * inv, acc[11] * inv);
    *(float4*)(op + 12) = make_float4(acc[12] * inv, acc[13] * inv, acc[14] * inv, acc[15] * inv);
}

// ---------------------------------------------------------------------------
extern "C" void kernel_launch(void* const* d_in, const int* in_sizes, int n_in,
                              void* d_out, int out_size)
{
    const float* x          = (const float*)d_in[0];
    const unsigned char* mk = (const unsigned char*)d_in[1];
    const float* Wq         = (const float*)d_in[2];
    const float* Wk         = (const float*)d_in[3];
    const float* Wv         = (const float*)d_in[4];
    const float* Wo         = (const float*)d_in[5];
    float* out              = (float*)d_out;

    float *qp, *kp, *vp, *ap;
    unsigned char* mkc;
    cudaGetSymbolAddress((void**)&qp, g_q);
    cudaGetSymbolAddress((void**)&kp, g_k);
    cudaGetSymbolAddress((void**)&vp, g_v);
    cudaGetSymbolAddress((void**)&ap, g_attn);
    cudaGetSymbolAddress((void**)&mkc, g_mask);

    mask_convert_kernel<<<64, 256>>>(mk);

    dim3 ggrid(Dc / 128, BT / 128);   // (8, 128)
    gemm_nt_kernel<<<ggrid, 256>>>(x, Wq, qp, mkc, 1);
    gemm_nt_kernel<<<ggrid, 256>>>(x, Wk, kp, mkc, 2);
    gemm_nt_kernel<<<ggrid, 256>>>(x, Wv, vp, mkc, 3);
    kv_partial_kernel<<<dim3(BH, SPLIT), 256>>>();
    kv_reduce_kernel<<<BH, 256>>>();
    attn_out_kernel<<<dim3(Tc / 64, BH), 256>>>();
    gemm_nt_kernel<<<ggrid, 256>>>(ap, Wo, out, mkc, 0);
}

// round 5
// speedup vs baseline: 1.7331x; 1.7331x over previous
#include <cuda_runtime.h>
#include <cuda_bf16.h>
#include <math.h>
#include <stdint.h>

// Problem constants
constexpr int Bc = 4, Tc = 4096, Dc = 1024, Hc = 16, HDc = 64;
constexpr int BT = Bc * Tc;          // 16384 rows
constexpr int BH = Bc * Hc;          // 64 (b,h) pairs
constexpr int SPLIT = 8;             // T-split for kv reduction

// Scratch (device globals: no allocation allowed in kernel_launch)
__device__ float g_q[BT * Dc];
__device__ float g_k[BT * Dc];
__device__ float g_v[BT * Dc];
__device__ float g_attn[BT * Dc];
__device__ float g_kvp[BH * SPLIT * HDc * HDc];
__device__ float g_ksp[BH * SPLIT * HDc];
__device__ float g_kv[BH * HDc * HDc];
__device__ float g_ksum[BH * HDc];
__device__ unsigned char g_mask[BT];

__device__ __forceinline__ float phi(float x) {
    return x > 0.f ? x + 1.f : expf(x);
}

__device__ __forceinline__ uint32_t smem_u32(const void* p) {
    uint32_t a;
    asm("{ .reg .u64 t; cvta.to.shared.u64 t, %1; cvt.u32.u64 %0, t; }" : "=r"(a) : "l"(p));
    return a;
}

// pack two bf16 (from floats) into u32: x in low half, y in high half
__device__ __forceinline__ uint32_t pack_bf2(float x, float y) {
    __nv_bfloat162 h = __floats2bfloat162_rn(x, y);
    return *(uint32_t*)&h;
}

// ---------------------------------------------------------------------------
// 3-term bf16-split tensor-core GEMM: C = A @ W^T  (fp32 in/out)
// M=16384, N=K=1024. Per 32-fp32-K stage, smem row = [hi(64B) | lo(64B)].
// Computes aH*bH + aL*bH + aH*bL (drops aL*bL ~ 2^-18).
// Tile 128x128, 8 warps (4m x 2n), warp tile 32x64, mma.m16n8k16.bf16.
// op: 0 none, 1 phi, 2 phi+mask, 3 mask
// ---------------------------------------------------------------------------
constexpr int GSM_STAGE = 32768;                // A(16K) + B(16K) bf16 per stage
constexpr int GSM_TOTAL = 2 * GSM_STAGE;        // 64KB double-buffered

__global__ __launch_bounds__(256) void gemm_tc_kernel(
    const float* __restrict__ A, const float* __restrict__ W,
    float* __restrict__ C, const unsigned char* __restrict__ mask, int op)
{
    extern __shared__ __align__(1024) char smem[];
    const uint32_t sbase = smem_u32(smem);
    const int tid = threadIdx.x;
    const int wid = tid >> 5, lane = tid & 31;
    const int wm = wid & 3, wn = wid >> 2;
    const int brow = blockIdx.y, bcol = blockIdx.x;

    const float* Ap = A + (size_t)brow * 128 * 1024;
    const float* Wp = W + (size_t)bcol * 128 * 1024;

    // fill mapping: thread handles 4 float4 (4 rows x 4 fp32 each)
    const int fr[4] = { (tid + 0) >> 3, (tid + 256) >> 3, (tid + 512) >> 3, (tid + 768) >> 3 };
    const int fc4 = (tid & 7) * 4;                  // fp32 col offset 0..28
    // hi bytes at col fc4*2 (0..56), lo bytes at 64 + fc4*2
    uint32_t offH[4], offL[4];
#pragma unroll
    for (int i = 0; i < 4; i++) {
        uint32_t sw = (uint32_t)((fr[i] & 7) << 4);
        offH[i] = ((uint32_t)(fr[i] * 128 + fc4 * 2)) ^ sw;
        offL[i] = ((uint32_t)(fr[i] * 128 + 64 + fc4 * 2)) ^ sw;
    }

    float4 ra[4], rb[4];
#pragma unroll
    for (int i = 0; i < 4; i++) {
        ra[i] = *(const float4*)(Ap + (size_t)fr[i] * 1024 + fc4);
        rb[i] = *(const float4*)(Wp + (size_t)fr[i] * 1024 + fc4);
    }

    auto store_stage = [&](char* s, const float4* va, const float4* vb) {
#pragma unroll
        for (int i = 0; i < 4; i++) {
            // A
            float hx = __bfloat162float(__float2bfloat16(va[i].x));
            float hy = __bfloat162float(__float2bfloat16(va[i].y));
            float hz = __bfloat162float(__float2bfloat16(va[i].z));
            float hw = __bfloat162float(__float2bfloat16(va[i].w));
            uint2 ph = make_uint2(pack_bf2(va[i].x, va[i].y), pack_bf2(va[i].z, va[i].w));
            uint2 pl = make_uint2(pack_bf2(va[i].x - hx, va[i].y - hy),
                                  pack_bf2(va[i].z - hz, va[i].w - hw));
            *(uint2*)(s + offH[i]) = ph;
            *(uint2*)(s + offL[i]) = pl;
            // B
            hx = __bfloat162float(__float2bfloat16(vb[i].x));
            hy = __bfloat162float(__float2bfloat16(vb[i].y));
            hz = __bfloat162float(__float2bfloat16(vb[i].z));
            hw = __bfloat162float(__float2bfloat16(vb[i].w));
            ph = make_uint2(pack_bf2(vb[i].x, vb[i].y), pack_bf2(vb[i].z, vb[i].w));
            pl = make_uint2(pack_bf2(vb[i].x - hx, vb[i].y - hy),
                            pack_bf2(vb[i].z - hz, vb[i].w - hw));
            *(uint2*)(s + 16384 + offH[i]) = ph;
            *(uint2*)(s + 16384 + offL[i]) = pl;
        }
    };

    store_stage(smem, ra, rb);
    __syncthreads();

    float acc[2][8][4];
#pragma unroll
    for (int mt = 0; mt < 2; mt++)
#pragma unroll
        for (int nt = 0; nt < 8; nt++)
#pragma unroll
            for (int j = 0; j < 4; j++) acc[mt][nt][j] = 0.f;

    const int lrow = lane & 7;
    const int seg = lane >> 3;
    const int segr = (seg & 1) << 3;        // +8 rows for segments 1,3
    const int segc = (seg & 2) << 3;        // +16 bytes for segs 2,3

    constexpr int NT = 32;                  // K / 32
#pragma unroll 1
    for (int t = 0; t < NT; t++) {
        const int buf = t & 1;
        const uint32_t sA = sbase + buf * GSM_STAGE;
        const uint32_t sB = sA + 16384;

        if (t + 1 < NT) {
#pragma unroll
            for (int i = 0; i < 4; i++) {
                ra[i] = *(const float4*)(Ap + (size_t)fr[i] * 1024 + (t + 1) * 32 + fc4);
                rb[i] = *(const float4*)(Wp + (size_t)fr[i] * 1024 + (t + 1) * 32 + fc4);
            }
        }

#pragma unroll
        for (int ks2 = 0; ks2 < 2; ks2++) {
            const int cH = ks2 * 32 + segc;        // hi byte col
            const int cL = 64 + cH;                // lo byte col

            uint32_t afrH[2][4], afrL[2][4];
#pragma unroll
            for (int mt = 0; mt < 2; mt++) {
                int row = wm * 32 + mt * 16 + lrow + segr;
                uint32_t sw = (uint32_t)((row & 7) << 4);
                uint32_t oh = ((uint32_t)(row * 128 + cH)) ^ sw;
                uint32_t ol = ((uint32_t)(row * 128 + cL)) ^ sw;
                asm volatile("ldmatrix.sync.aligned.m8n8.x4.shared.b16 {%0,%1,%2,%3}, [%4];"
                    : "=r"(afrH[mt][0]), "=r"(afrH[mt][1]), "=r"(afrH[mt][2]), "=r"(afrH[mt][3])
                    : "r"(sA + oh));
                asm volatile("ldmatrix.sync.aligned.m8n8.x4.shared.b16 {%0,%1,%2,%3}, [%4];"
                    : "=r"(afrL[mt][0]), "=r"(afrL[mt][1]), "=r"(afrL[mt][2]), "=r"(afrL[mt][3])
                    : "r"(sA + ol));
            }

            uint32_t bfr[4][4];
            // --- B-hi block: aH*bH and aL*bH ---
#pragma unroll
            for (int nt2 = 0; nt2 < 4; nt2++) {
                int row = wn * 64 + nt2 * 16 + lrow + segr;
                uint32_t off = ((uint32_t)(row * 128 + cH)) ^ (uint32_t)((row & 7) << 4);
                asm volatile("ldmatrix.sync.aligned.m8n8.x4.shared.b16 {%0,%1,%2,%3}, [%4];"
                    : "=r"(bfr[nt2][0]), "=r"(bfr[nt2][1]), "=r"(bfr[nt2][2]), "=r"(bfr[nt2][3])
                    : "r"(sB + off));
            }
#pragma unroll
            for (int mt = 0; mt < 2; mt++)
#pragma unroll
                for (int nt = 0; nt < 8; nt++) {
                    const int g = nt >> 1, h = nt & 1;
                    asm volatile(
                        "mma.sync.aligned.m16n8k16.row.col.f32.bf16.bf16.f32 "
                        "{%0,%1,%2,%3}, {%4,%5,%6,%7}, {%8,%9}, {%0,%1,%2,%3};"
                        : "+f"(acc[mt][nt][0]), "+f"(acc[mt][nt][1]),
                          "+f"(acc[mt][nt][2]), "+f"(acc[mt][nt][3])
                        : "r"(afrH[mt][0]), "r"(afrH[mt][1]), "r"(afrH[mt][2]), "r"(afrH[mt][3]),
                          "r"(bfr[g][h]), "r"(bfr[g][h + 2]));
                    asm volatile(
                        "mma.sync.aligned.m16n8k16.row.col.f32.bf16.bf16.f32 "
                        "{%0,%1,%2,%3}, {%4,%5,%6,%7}, {%8,%9}, {%0,%1,%2,%3};"
                        : "+f"(acc[mt][nt][0]), "+f"(acc[mt][nt][1]),
                          "+f"(acc[mt][nt][2]), "+f"(acc[mt][nt][3])
                        : "r"(afrL[mt][0]), "r"(afrL[mt][1]), "r"(afrL[mt][2]), "r"(afrL[mt][3]),
                          "r"(bfr[g][h]), "r"(bfr[g][h + 2]));
                }

            // --- B-lo block: aH*bL ---
#pragma unroll
            for (int nt2 = 0; nt2 < 4; nt2++) {
                int row = wn * 64 + nt2 * 16 + lrow + segr;
                uint32_t off = ((uint32_t)(row * 128 + cL)) ^ (uint32_t)((row & 7) << 4);
                asm volatile("ldmatrix.sync.aligned.m8n8.x4.shared.b16 {%0,%1,%2,%3}, [%4];"
                    : "=r"(bfr[nt2][0]), "=r"(bfr[nt2][1]), "=r"(bfr[nt2][2]), "=r"(bfr[nt2][3])
                    : "r"(sB + off));
            }
#pragma unroll
            for (int mt = 0; mt < 2; mt++)
#pragma unroll
                for (int nt = 0; nt < 8; nt++) {
                    const int g = nt >> 1, h = nt & 1;
                    asm volatile(
                        "mma.sync.aligned.m16n8k16.row.col.f32.bf16.bf16.f32 "
                        "{%0,%1,%2,%3}, {%4,%5,%6,%7}, {%8,%9}, {%0,%1,%2,%3};"
                        : "+f"(acc[mt][nt][0]), "+f"(acc[mt][nt][1]),
                          "+f"(acc[mt][nt][2]), "+f"(acc[mt][nt][3])
                        : "r"(afrH[mt][0]), "r"(afrH[mt][1]), "r"(afrH[mt][2]), "r"(afrH[mt][3]),
                          "r"(bfr[g][h]), "r"(bfr[g][h + 2]));
                }
        }

        if (t + 1 < NT) {
            store_stage(smem + (1 - buf) * GSM_STAGE, ra, rb);
            __syncthreads();
        }
    }

    // Epilogue
    const int r0 = brow * 128 + wm * 32 + (lane >> 2);
    const int c0 = bcol * 128 + wn * 64 + (lane & 3) * 2;
    const bool do_phi = (op == 1 || op == 2);
    const bool do_msk = (op >= 2);
#pragma unroll
    for (int mt = 0; mt < 2; mt++) {
        const int r = r0 + mt * 16;
        const bool mz0 = do_msk && (mask[r] != 0);
        const bool mz1 = do_msk && (mask[r + 8] != 0);
#pragma unroll
        for (int nt = 0; nt < 8; nt++) {
            float2 v0 = make_float2(acc[mt][nt][0], acc[mt][nt][1]);
            float2 v1 = make_float2(acc[mt][nt][2], acc[mt][nt][3]);
            if (do_phi) {
                v0.x = phi(v0.x); v0.y = phi(v0.y);
                v1.x = phi(v1.x); v1.y = phi(v1.y);
            }
            if (mz0) { v0.x = 0.f; v0.y = 0.f; }
            if (mz1) { v1.x = 0.f; v1.y = 0.f; }
            *(float2*)(C + (size_t)r * 1024 + c0 + nt * 8) = v0;
            *(float2*)(C + (size_t)(r + 8) * 1024 + c0 + nt * 8) = v1;
        }
    }
}

// ---------------------------------------------------------------------------
// Mask normalization (dtype-agnostic) -> uint8 0/1
// ---------------------------------------------------------------------------
__global__ __launch_bounds__(256) void mask_convert_kernel(const unsigned char* __restrict__ mraw)
{
    __shared__ int s_float, s_odd;
    if (threadIdx.x == 0) { s_float = 0; s_odd = 0; }
    __syncthreads();
    for (int i = threadIdx.x; i < 4096; i += 256) {
        unsigned char v = mraw[i];
        if (v == 0x3F) s_float = 1;
        if (v != 0 && (i & 3) != 0) s_odd = 1;
    }
    __syncthreads();
    const int dtype = s_float ? 2 : (s_odd ? 0 : 1);

    const int m0 = blockIdx.x * 256 + threadIdx.x;
    for (int m = m0; m < BT; m += 64 * 256) {
        unsigned char r;
        if (dtype == 0)      r = (mraw[m] != 0);
        else if (dtype == 1) r = (((const int*)mraw)[m] != 0);
        else                 r = (((const float*)mraw)[m] != 0.0f);
        g_mask[m] = r;
    }
}

// ---------------------------------------------------------------------------
// kv partial: for (b,h,split): kv[d][e] += k[t,d]*v[t,e]; ksum[d] += k[t,d]
// ---------------------------------------------------------------------------
__global__ __launch_bounds__(256) void kv_partial_kernel()
{
    const int tid = threadIdx.x;
    const int bh = blockIdx.x, sy = blockIdx.y;
    const int b = bh >> 4, h = bh & 15;
    const int t0 = sy * (Tc / SPLIT);

    __shared__ __align__(16) float Ks[32][64];
    __shared__ __align__(16) float Vs[32][64];

    float acc[16];
#pragma unroll
    for (int j = 0; j < 16; j++) acc[j] = 0.f;
    float ks = 0.f;

    const int d = tid >> 2;
    const int eb = (tid & 3) * 16;
    const size_t base = ((size_t)b * Tc) * Dc + h * 64;

    for (int tc = 0; tc < Tc / SPLIT; tc += 32) {
#pragma unroll
        for (int it = 0; it < 2; it++) {
            int i = tid + it * 256;
            int tl = i >> 4;
            int c4 = (i & 15) * 4;
            size_t off = base + (size_t)(t0 + tc + tl) * Dc + c4;
            *(float4*)&Ks[tl][c4] = *(const float4*)(g_k + off);
            *(float4*)&Vs[tl][c4] = *(const float4*)(g_v + off);
        }
        __syncthreads();
#pragma unroll
        for (int t = 0; t < 32; t++) {
            float kd = Ks[t][d];
            ks += kd;
            float4 v0 = *(const float4*)&Vs[t][eb];
            float4 v1 = *(const float4*)&Vs[t][eb + 4];
            float4 v2 = *(const float4*)&Vs[t][eb + 8];
            float4 v3 = *(const float4*)&Vs[t][eb + 12];
            acc[0]  = fmaf(kd, v0.x, acc[0]);  acc[1]  = fmaf(kd, v0.y, acc[1]);
            acc[2]  = fmaf(kd, v0.z, acc[2]);  acc[3]  = fmaf(kd, v0.w, acc[3]);
            acc[4]  = fmaf(kd, v1.x, acc[4]);  acc[5]  = fmaf(kd, v1.y, acc[5]);
            acc[6]  = fmaf(kd, v1.z, acc[6]);  acc[7]  = fmaf(kd, v1.w, acc[7]);
            acc[8]  = fmaf(kd, v2.x, acc[8]);  acc[9]  = fmaf(kd, v2.y, acc[9]);
            acc[10] = fmaf(kd, v2.z, acc[10]); acc[11] = fmaf(kd, v2.w, acc[11]);
            acc[12] = fmaf(kd, v3.x, acc[12]); acc[13] = fmaf(kd, v3.y, acc[13]);
            acc[14] = fmaf(kd, v3.z, acc[14]); acc[15] = fmaf(kd, v3.w, acc[15]);
        }
        __syncthreads();
    }

    float* outp = g_kvp + ((size_t)(bh * SPLIT + sy)) * 4096 + d * 64 + eb;
    *(float4*)(outp + 0)  = make_float4(acc[0], acc[1], acc[2], acc[3]);
    *(float4*)(outp + 4)  = make_float4(acc[4], acc[5], acc[6], acc[7]);
    *(float4*)(outp + 8)  = make_float4(acc[8], acc[9], acc[10], acc[11]);
    *(float4*)(outp + 12) = make_float4(acc[12], acc[13], acc[14], acc[15]);
    if ((tid & 3) == 0)
        g_ksp[(bh * SPLIT + sy) * 64 + d] = ks;
}

// ---------------------------------------------------------------------------
__global__ __launch_bounds__(256) void kv_reduce_kernel()
{
    const int bh = blockIdx.x, tid = threadIdx.x;
#pragma unroll
    for (int j = 0; j < 4; j++) {
        int off = tid * 16 + j * 4;
        float4 s = make_float4(0.f, 0.f, 0.f, 0.f);
#pragma unroll
        for (int sp = 0; sp < SPLIT; sp++) {
            float4 p = *(const float4*)(g_kvp + ((size_t)(bh * SPLIT + sp)) * 4096 + off);
            s.x += p.x; s.y += p.y; s.z += p.z; s.w += p.w;
        }
        *(float4*)(g_kv + (size_t)bh * 4096 + off) = s;
    }
    if (tid < 64) {
        float s = 0.f;
#pragma unroll
        for (int sp = 0; sp < SPLIT; sp++)
            s += g_ksp[(bh * SPLIT + sp) * 64 + tid];
        g_ksum[bh * 64 + tid] = s;
    }
}

// ---------------------------------------------------------------------------
__global__ __launch_bounds__(256) void attn_out_kernel()
{
    const int tid = threadIdx.x;
    const int bh = blockIdx.y;
    const int b = bh >> 4, h = bh & 15;
    const int t0 = blockIdx.x * 64;

    __shared__ __align__(16) float KV[4096];
    __shared__ float Qs[64][65];
    __shared__ float Ksm[64];

#pragma unroll
    for (int j = 0; j < 4; j++) {
        int f = tid + j * 256;
        *(float4*)&KV[f * 4] = *(const float4*)(g_kv + (size_t)bh * 4096 + f * 4);
    }
    if (tid < 64) Ksm[tid] = g_ksum[bh * 64 + tid];

    const size_t base = ((size_t)b * Tc) * Dc + h * 64;
#pragma unroll
    for (int j = 0; j < 16; j++) {
        int i = tid + j * 256;
        int tl = i >> 6, d = i & 63;
        Qs[d][tl] = g_q[base + (size_t)(t0 + tl) * Dc + d];
    }
    __syncthreads();

    const int tl = tid >> 2;
    const int eb = (tid & 3) * 16;
    float acc[16];
#pragma unroll
    for (int j = 0; j < 16; j++) acc[j] = 0.f;
    float nrm = 0.f;

#pragma unroll
    for (int d2 = 0; d2 < 64; d2++) {
        float qd = Qs[d2][tl];
        nrm = fmaf(qd, Ksm[d2], nrm);
        const float4* kvp = (const float4*)&KV[d2 * 64 + eb];
        float4 v0 = kvp[0], v1 = kvp[1], v2 = kvp[2], v3 = kvp[3];
        acc[0]  = fmaf(qd, v0.x, acc[0]);  acc[1]  = fmaf(qd, v0.y, acc[1]);
        acc[2]  = fmaf(qd, v0.z, acc[2]);  acc[3]  = fmaf(qd, v0.w, acc[3]);
        acc[4]  = fmaf(qd, v1.x, acc[4]);  acc[5]  = fmaf(qd, v1.y, acc[5]);
        acc[6]  = fmaf(qd, v1.z, acc[6]);  acc[7]  = fmaf(qd, v1.w, acc[7]);
        acc[8]  = fmaf(qd, v2.x, acc[8]);  acc[9]  = fmaf(qd, v2.y, acc[9]);
        acc[10] = fmaf(qd, v2.z, acc[10]); acc[11] = fmaf(qd, v2.w, acc[11]);
        acc[12] = fmaf(qd, v3.x, acc[12]); acc[13] = fmaf(qd, v3.y, acc[13]);
        acc[14] = fmaf(qd, v3.z, acc[14]); acc[15] = fmaf(qd, v3.w, acc[15]);
    }

    float inv = 1.f / fmaxf(nrm, 1e-6f);
    float* op = g_attn + base + (size_t)(t0 + tl) * Dc + eb;
    *(float4*)(op + 0)  = make_float4(acc[0] * inv, acc[1] * inv, acc[2] * inv, acc[3] * inv);
    *(float4*)(op + 4)  = make_float4(acc[4] * inv, acc[5] * inv, acc[6] * inv, acc[7] * inv);
    *(float4*)(op + 8)  = make_float4(acc[8] * inv, acc[9] * inv, acc[10] * inv, acc[11] * inv);
    *(float4*)(op + 12) = make_float4(acc[12] * inv, acc[13] * inv, acc[14] * inv, acc[15] * inv);
}

// ---------------------------------------------------------------------------
extern "C" void kernel_launch(void* const* d_in, const int* in_sizes, int n_in,
                              void* d_out, int out_size)
{
    const float* x          = (const float*)d_in[0];
    const unsigned char* mk = (const unsigned char*)d_in[1];
    const float* Wq         = (const float*)d_in[2];
    const float* Wk         = (const float*)d_in[3];
    const float* Wv         = (const float*)d_in[4];
    const float* Wo         = (const float*)d_in[5];
    float* out              = (float*)d_out;

    float *qp, *kp, *vp, *ap;
    unsigned char* mkc;
    cudaGetSymbolAddress((void**)&qp, g_q);
    cudaGetSymbolAddress((void**)&kp, g_k);
    cudaGetSymbolAddress((void**)&vp, g_v);
    cudaGetSymbolAddress((void**)&ap, g_attn);
    cudaGetSymbolAddress((void**)&mkc, g_mask);

    cudaFuncSetAttribute(gemm_tc_kernel,
                         cudaFuncAttributeMaxDynamicSharedMemorySize, GSM_TOTAL);

    mask_convert_kernel<<<64, 256>>>(mk);

    dim3 ggrid(Dc / 128, BT / 128);   // (8, 128)
    gemm_tc_kernel<<<ggrid, 256, GSM_TOTAL>>>(x, Wq, qp, mkc, 1);
    gemm_tc_kernel<<<ggrid, 256, GSM_TOTAL>>>(x, Wk, kp, mkc, 2);
    gemm_tc_kernel<<<ggrid, 256, GSM_TOTAL>>>(x, Wv, vp, mkc, 3);
    kv_partial_kernel<<<dim3(BH, SPLIT), 256>>>();
    kv_reduce_kernel<<<BH, 256>>>();
    attn_out_kernel<<<dim3(Tc / 64, BH), 256>>>();
    gemm_tc_kernel<<<ggrid, 256, GSM_TOTAL>>>(ap, Wo, out, mkc, 0);
}

// round 6
// speedup vs baseline: 1.9556x; 1.1284x over previous
#include <cuda_runtime.h>
#include <cuda_bf16.h>
#include <math.h>
#include <stdint.h>

// Problem constants
constexpr int Bc = 4, Tc = 4096, Dc = 1024, Hc = 16, HDc = 64;
constexpr int BT = Bc * Tc;          // 16384 rows
constexpr int BH = Bc * Hc;          // 64 (b,h) pairs
constexpr int SPLIT = 32;            // T-split for kv reduction

// Scratch (device globals: no allocation allowed in kernel_launch)
__device__ float g_q[BT * Dc];
__device__ float g_k[BT * Dc];
__device__ float g_v[BT * Dc];
__device__ float g_kvp[BH * SPLIT * HDc * HDc];
__device__ float g_ksp[BH * SPLIT * HDc];
__device__ float g_kv[BH * HDc * HDc];
__device__ float g_ksum[BH * HDc];
__device__ unsigned char g_mask[BT];
// bf16 hi/lo split operand buffers
__device__ __nv_bfloat16 g_xh[BT * Dc], g_xl[BT * Dc];
__device__ __nv_bfloat16 g_ah[BT * Dc], g_al[BT * Dc];
__device__ __nv_bfloat16 g_wh[4][Dc * Dc], g_wl[4][Dc * Dc];

__device__ __forceinline__ float phi(float x) {
    return x > 0.f ? x + 1.f : expf(x);
}

__device__ __forceinline__ uint32_t smem_u32(const void* p) {
    uint32_t a;
    asm("{ .reg .u64 t; cvta.to.shared.u64 t, %1; cvt.u32.u64 %0, t; }" : "=r"(a) : "l"(p));
    return a;
}

// pack two bf16 (from floats) into u32: x low, y high
__device__ __forceinline__ uint32_t pack_bf2(float x, float y) {
    __nv_bfloat162 h = __floats2bfloat162_rn(x, y);
    return *(uint32_t*)&h;
}

__device__ __forceinline__ void cp16(uint32_t dst, const void* src) {
    asm volatile("cp.async.cg.shared.global [%0], [%1], 16;" :: "r"(dst), "l"(src));
}
#define CP_COMMIT() asm volatile("cp.async.commit_group;" ::: "memory")
#define CP_WAIT2()  asm volatile("cp.async.wait_group 2;" ::: "memory")

// ---------------------------------------------------------------------------
// fp32 -> (hi, lo) bf16 split, vectorized
// ---------------------------------------------------------------------------
__global__ __launch_bounds__(256) void split_kernel(
    const float4* __restrict__ src, uint2* __restrict__ hi, uint2* __restrict__ lo, int n4)
{
    for (int i = blockIdx.x * 256 + threadIdx.x; i < n4; i += gridDim.x * 256) {
        float4 v = src[i];
        float hx = __bfloat162float(__float2bfloat16(v.x));
        float hy = __bfloat162float(__float2bfloat16(v.y));
        float hz = __bfloat162float(__float2bfloat16(v.z));
        float hw = __bfloat162float(__float2bfloat16(v.w));
        hi[i] = make_uint2(pack_bf2(v.x, v.y), pack_bf2(v.z, v.w));
        lo[i] = make_uint2(pack_bf2(v.x - hx, v.y - hy), pack_bf2(v.z - hz, v.w - hw));
    }
}

// ---------------------------------------------------------------------------
// 3-term bf16-split tensor-core GEMM, operands pre-split in global bf16.
// C[M,N] = A @ B^T, M=16384, N=K=1024. Tile 128x128, 8 warps (4m x 2n),
// warp tile 32x64, mma.m16n8k16.bf16, cp.async 4-stage pipeline.
// smem stage (32KB): A rows [hi 64B | lo 64B] (16KB) then B (16KB).
// op: 0 none, 1 phi, 2 phi+mask, 3 mask
// ---------------------------------------------------------------------------
constexpr int GSM_STAGE = 32768;
constexpr int NSTAGES = 4;
constexpr int GSM_TOTAL = NSTAGES * GSM_STAGE;   // 128KB

__global__ __launch_bounds__(256) void gemm_tc_kernel(
    const __nv_bfloat16* __restrict__ Ah, const __nv_bfloat16* __restrict__ Al,
    const __nv_bfloat16* __restrict__ Bh, const __nv_bfloat16* __restrict__ Bl,
    float* __restrict__ C, const unsigned char* __restrict__ mask, int op)
{
    extern __shared__ __align__(1024) char smem[];
    const uint32_t sbase = smem_u32(smem);
    const int tid = threadIdx.x;
    const int wid = tid >> 5, lane = tid & 31;
    const int wm = wid & 3, wn = wid >> 2;
    const int brow = blockIdx.y, bcol = blockIdx.x;

    // loader mapping: each thread owns (part, ci) and 4 rows r0+32i for A and B
    const int r0 = tid >> 3;            // 0..31
    const int part = (tid >> 2) & 1;    // 0 = hi, 1 = lo
    const int ci = tid & 3;             // 16B chunk within 64B half-row
    const __nv_bfloat16* srcA = (part ? Al : Ah) + (size_t)(brow * 128) * 1024;
    const __nv_bfloat16* srcB = (part ? Bl : Bh) + (size_t)(bcol * 128) * 1024;
    uint32_t dstA[4];
#pragma unroll
    for (int i = 0; i < 4; i++) {
        int row = r0 + 32 * i;
        dstA[i] = ((uint32_t)(row * 128 + part * 64 + ci * 16)) ^ (uint32_t)((row & 7) << 4);
    }

    auto load_stage = [&](int s, int buf) {
        uint32_t sb = sbase + buf * GSM_STAGE;
        const int koff = s * 32 + ci * 8;
#pragma unroll
        for (int i = 0; i < 4; i++) {
            int row = r0 + 32 * i;
            cp16(sb + dstA[i], srcA + (size_t)row * 1024 + koff);
            cp16(sb + 16384 + dstA[i], srcB + (size_t)row * 1024 + koff);
        }
    };

    // prologue: stages 0..2
#pragma unroll
    for (int s = 0; s < NSTAGES - 1; s++) {
        load_stage(s, s);
        CP_COMMIT();
    }

    float acc[2][8][4];
#pragma unroll
    for (int mt = 0; mt < 2; mt++)
#pragma unroll
        for (int nt = 0; nt < 8; nt++)
#pragma unroll
            for (int j = 0; j < 4; j++) acc[mt][nt][j] = 0.f;

    const int lrow = lane & 7;
    const int seg = lane >> 3;
    const int segr = (seg & 1) << 3;
    const int segc = (seg & 2) << 3;

    constexpr int NT = 32;
#pragma unroll 1
    for (int t = 0; t < NT; t++) {
        CP_WAIT2();
        __syncthreads();
        if (t + NSTAGES - 1 < NT) load_stage(t + NSTAGES - 1, (t + NSTAGES - 1) & (NSTAGES - 1));
        CP_COMMIT();

        const uint32_t sA = sbase + (t & (NSTAGES - 1)) * GSM_STAGE;
        const uint32_t sB = sA + 16384;

#pragma unroll
        for (int ks2 = 0; ks2 < 2; ks2++) {
            const int cH = ks2 * 32 + segc;
            const int cL = 64 + cH;

            uint32_t afrH[2][4], afrL[2][4];
#pragma unroll
            for (int mt = 0; mt < 2; mt++) {
                int row = wm * 32 + mt * 16 + lrow + segr;
                uint32_t sw = (uint32_t)((row & 7) << 4);
                uint32_t oh = ((uint32_t)(row * 128 + cH)) ^ sw;
                uint32_t ol = ((uint32_t)(row * 128 + cL)) ^ sw;
                asm volatile("ldmatrix.sync.aligned.m8n8.x4.shared.b16 {%0,%1,%2,%3}, [%4];"
                    : "=r"(afrH[mt][0]), "=r"(afrH[mt][1]), "=r"(afrH[mt][2]), "=r"(afrH[mt][3])
                    : "r"(sA + oh));
                asm volatile("ldmatrix.sync.aligned.m8n8.x4.shared.b16 {%0,%1,%2,%3}, [%4];"
                    : "=r"(afrL[mt][0]), "=r"(afrL[mt][1]), "=r"(afrL[mt][2]), "=r"(afrL[mt][3])
                    : "r"(sA + ol));
            }

            uint32_t bfr[4][4];
            // --- B-hi block: aH*bH and aL*bH ---
#pragma unroll
            for (int nt2 = 0; nt2 < 4; nt2++) {
                int row = wn * 64 + nt2 * 16 + lrow + segr;
                uint32_t off = ((uint32_t)(row * 128 + cH)) ^ (uint32_t)((row & 7) << 4);
                asm volatile("ldmatrix.sync.aligned.m8n8.x4.shared.b16 {%0,%1,%2,%3}, [%4];"
                    : "=r"(bfr[nt2][0]), "=r"(bfr[nt2][1]), "=r"(bfr[nt2][2]), "=r"(bfr[nt2][3])
                    : "r"(sB + off));
            }
#pragma unroll
            for (int mt = 0; mt < 2; mt++)
#pragma unroll
                for (int nt = 0; nt < 8; nt++) {
                    const int g = nt >> 1, h = nt & 1;
                    asm volatile(
                        "mma.sync.aligned.m16n8k16.row.col.f32.bf16.bf16.f32 "
                        "{%0,%1,%2,%3}, {%4,%5,%6,%7}, {%8,%9}, {%0,%1,%2,%3};"
                        : "+f"(acc[mt][nt][0]), "+f"(acc[mt][nt][1]),
                          "+f"(acc[mt][nt][2]), "+f"(acc[mt][nt][3])
                        : "r"(afrH[mt][0]), "r"(afrH[mt][1]), "r"(afrH[mt][2]), "r"(afrH[mt][3]),
                          "r"(bfr[g][h]), "r"(bfr[g][h + 2]));
                    asm volatile(
                        "mma.sync.aligned.m16n8k16.row.col.f32.bf16.bf16.f32 "
                        "{%0,%1,%2,%3}, {%4,%5,%6,%7}, {%8,%9}, {%0,%1,%2,%3};"
                        : "+f"(acc[mt][nt][0]), "+f"(acc[mt][nt][1]),
                          "+f"(acc[mt][nt][2]), "+f"(acc[mt][nt][3])
                        : "r"(afrL[mt][0]), "r"(afrL[mt][1]), "r"(afrL[mt][2]), "r"(afrL[mt][3]),
                          "r"(bfr[g][h]), "r"(bfr[g][h + 2]));
                }

            // --- B-lo block: aH*bL ---
#pragma unroll
            for (int nt2 = 0; nt2 < 4; nt2++) {
                int row = wn * 64 + nt2 * 16 + lrow + segr;
                uint32_t off = ((uint32_t)(row * 128 + cL)) ^ (uint32_t)((row & 7) << 4);
                asm volatile("ldmatrix.sync.aligned.m8n8.x4.shared.b16 {%0,%1,%2,%3}, [%4];"
                    : "=r"(bfr[nt2][0]), "=r"(bfr[nt2][1]), "=r"(bfr[nt2][2]), "=r"(bfr[nt2][3])
                    : "r"(sB + off));
            }
#pragma unroll
            for (int mt = 0; mt < 2; mt++)
#pragma unroll
                for (int nt = 0; nt < 8; nt++) {
                    const int g = nt >> 1, h = nt & 1;
                    asm volatile(
                        "mma.sync.aligned.m16n8k16.row.col.f32.bf16.bf16.f32 "
                        "{%0,%1,%2,%3}, {%4,%5,%6,%7}, {%8,%9}, {%0,%1,%2,%3};"
                        : "+f"(acc[mt][nt][0]), "+f"(acc[mt][nt][1]),
                          "+f"(acc[mt][nt][2]), "+f"(acc[mt][nt][3])
                        : "r"(afrH[mt][0]), "r"(afrH[mt][1]), "r"(afrH[mt][2]), "r"(afrH[mt][3]),
                          "r"(bfr[g][h]), "r"(bfr[g][h + 2]));
                }
        }
    }

    // Epilogue
    const int r0e = brow * 128 + wm * 32 + (lane >> 2);
    const int c0 = bcol * 128 + wn * 64 + (lane & 3) * 2;
    const bool do_phi = (op == 1 || op == 2);
    const bool do_msk = (op >= 2);
#pragma unroll
    for (int mt = 0; mt < 2; mt++) {
        const int r = r0e + mt * 16;
        const bool mz0 = do_msk && (mask[r] != 0);
        const bool mz1 = do_msk && (mask[r + 8] != 0);
#pragma unroll
        for (int nt = 0; nt < 8; nt++) {
            float2 v0 = make_float2(acc[mt][nt][0], acc[mt][nt][1]);
            float2 v1 = make_float2(acc[mt][nt][2], acc[mt][nt][3]);
            if (do_phi) {
                v0.x = phi(v0.x); v0.y = phi(v0.y);
                v1.x = phi(v1.x); v1.y = phi(v1.y);
            }
            if (mz0) { v0.x = 0.f; v0.y = 0.f; }
            if (mz1) { v1.x = 0.f; v1.y = 0.f; }
            *(float2*)(C + (size_t)r * 1024 + c0 + nt * 8) = v0;
            *(float2*)(C + (size_t)(r + 8) * 1024 + c0 + nt * 8) = v1;
        }
    }
}

// ---------------------------------------------------------------------------
// Mask normalization (dtype-agnostic) -> uint8 0/1
// ---------------------------------------------------------------------------
__global__ __launch_bounds__(256) void mask_convert_kernel(const unsigned char* __restrict__ mraw)
{
    __shared__ int s_float, s_odd;
    if (threadIdx.x == 0) { s_float = 0; s_odd = 0; }
    __syncthreads();
    for (int i = threadIdx.x; i < 4096; i += 256) {
        unsigned char v = mraw[i];
        if (v == 0x3F) s_float = 1;
        if (v != 0 && (i & 3) != 0) s_odd = 1;
    }
    __syncthreads();
    const int dtype = s_float ? 2 : (s_odd ? 0 : 1);

    const int m0 = blockIdx.x * 256 + threadIdx.x;
    for (int m = m0; m < BT; m += 64 * 256) {
        unsigned char r;
        if (dtype == 0)      r = (mraw[m] != 0);
        else if (dtype == 1) r = (((const int*)mraw)[m] != 0);
        else                 r = (((const float*)mraw)[m] != 0.0f);
        g_mask[m] = r;
    }
}

// ---------------------------------------------------------------------------
// kv partial: for (b,h,split): kv[d][e] += k[t,d]*v[t,e]; ksum[d] += k[t,d]
// grid (BH, SPLIT), 256 threads
// ---------------------------------------------------------------------------
__global__ __launch_bounds__(256) void kv_partial_kernel()
{
    const int tid = threadIdx.x;
    const int bh = blockIdx.x, sy = blockIdx.y;
    const int b = bh >> 4, h = bh & 15;
    const int t0 = sy * (Tc / SPLIT);

    __shared__ __align__(16) float Ks[32][64];
    __shared__ __align__(16) float Vs[32][64];

    float acc[16];
#pragma unroll
    for (int j = 0; j < 16; j++) acc[j] = 0.f;
    float ks = 0.f;

    const int d = tid >> 2;
    const int eb = (tid & 3) * 16;
    const size_t base = ((size_t)b * Tc) * Dc + h * 64;

    for (int tc = 0; tc < Tc / SPLIT; tc += 32) {
#pragma unroll
        for (int it = 0; it < 2; it++) {
            int i = tid + it * 256;
            int tl = i >> 4;
            int c4 = (i & 15) * 4;
            size_t off = base + (size_t)(t0 + tc + tl) * Dc + c4;
            *(float4*)&Ks[tl][c4] = *(const float4*)(g_k + off);
            *(float4*)&Vs[tl][c4] = *(const float4*)(g_v + off);
        }
        __syncthreads();
#pragma unroll
        for (int t = 0; t < 32; t++) {
            float kd = Ks[t][d];
            ks += kd;
            float4 v0 = *(const float4*)&Vs[t][eb];
            float4 v1 = *(const float4*)&Vs[t][eb + 4];
            float4 v2 = *(const float4*)&Vs[t][eb + 8];
            float4 v3 = *(const float4*)&Vs[t][eb + 12];
            acc[0]  = fmaf(kd, v0.x, acc[0]);  acc[1]  = fmaf(kd, v0.y, acc[1]);
            acc[2]  = fmaf(kd, v0.z, acc[2]);  acc[3]  = fmaf(kd, v0.w, acc[3]);
            acc[4]  = fmaf(kd, v1.x, acc[4]);  acc[5]  = fmaf(kd, v1.y, acc[5]);
            acc[6]  = fmaf(kd, v1.z, acc[6]);  acc[7]  = fmaf(kd, v1.w, acc[7]);
            acc[8]  = fmaf(kd, v2.x, acc[8]);  acc[9]  = fmaf(kd, v2.y, acc[9]);
            acc[10] = fmaf(kd, v2.z, acc[10]); acc[11] = fmaf(kd, v2.w, acc[11]);
            acc[12] = fmaf(kd, v3.x, acc[12]); acc[13] = fmaf(kd, v3.y, acc[13]);
            acc[14] = fmaf(kd, v3.z, acc[14]); acc[15] = fmaf(kd, v3.w, acc[15]);
        }
        __syncthreads();
    }

    float* outp = g_kvp + ((size_t)(bh * SPLIT + sy)) * 4096 + d * 64 + eb;
    *(float4*)(outp + 0)  = make_float4(acc[0], acc[1], acc[2], acc[3]);
    *(float4*)(outp + 4)  = make_float4(acc[4], acc[5], acc[6], acc[7]);
    *(float4*)(outp + 8)  = make_float4(acc[8], acc[9], acc[10], acc[11]);
    *(float4*)(outp + 12) = make_float4(acc[12], acc[13], acc[14], acc[15]);
    if ((tid & 3) == 0)
        g_ksp[(bh * SPLIT + sy) * 64 + d] = ks;
}

// ---------------------------------------------------------------------------
__global__ __launch_bounds__(256) void kv_reduce_kernel()
{
    const int bh = blockIdx.x, tid = threadIdx.x;
#pragma unroll
    for (int j = 0; j < 4; j++) {
        int off = tid * 16 + j * 4;
        float4 s = make_float4(0.f, 0.f, 0.f, 0.f);
#pragma unroll
        for (int sp = 0; sp < SPLIT; sp++) {
            float4 p = *(const float4*)(g_kvp + ((size_t)(bh * SPLIT + sp)) * 4096 + off);
            s.x += p.x; s.y += p.y; s.z += p.z; s.w += p.w;
        }
        *(float4*)(g_kv + (size_t)bh * 4096 + off) = s;
    }
    if (tid < 64) {
        float s = 0.f;
#pragma unroll
        for (int sp = 0; sp < SPLIT; sp++)
            s += g_ksp[(bh * SPLIT + sp) * 64 + tid];
        g_ksum[bh * 64 + tid] = s;
    }
}

// ---------------------------------------------------------------------------
// attn out: out[t,e] = (sum_d q[t,d]*kv[d,e]) / max(q[t]·ksum, 1e-6)
// Writes bf16 hi/lo split directly (input of the final GEMM).
// ---------------------------------------------------------------------------
__global__ __launch_bounds__(256) void attn_out_kernel()
{
    const int tid = threadIdx.x;
    const int bh = blockIdx.y;
    const int b = bh >> 4, h = bh & 15;
    const int t0 = blockIdx.x * 64;

    __shared__ __align__(16) float KV[4096];
    __shared__ float Qs[64][65];
    __shared__ float Ksm[64];

#pragma unroll
    for (int j = 0; j < 4; j++) {
        int f = tid + j * 256;
        *(float4*)&KV[f * 4] = *(const float4*)(g_kv + (size_t)bh * 4096 + f * 4);
    }
    if (tid < 64) Ksm[tid] = g_ksum[bh * 64 + tid];

    const size_t base = ((size_t)b * Tc) * Dc + h * 64;
#pragma unroll
    for (int j = 0; j < 16; j++) {
        int i = tid + j * 256;
        int tl = i >> 6, d = i & 63;
        Qs[d][tl] = g_q[base + (size_t)(t0 + tl) * Dc + d];
    }
    __syncthreads();

    const int tl = tid >> 2;
    const int eb = (tid & 3) * 16;
    float acc[16];
#pragma unroll
    for (int j = 0; j < 16; j++) acc[j] = 0.f;
    float nrm = 0.f;

#pragma unroll
    for (int d2 = 0; d2 < 64; d2++) {
        float qd = Qs[d2][tl];
        nrm = fmaf(qd, Ksm[d2], nrm);
        const float4* kvp = (const float4*)&KV[d2 * 64 + eb];
        float4 v0 = kvp[0], v1 = kvp[1], v2 = kvp[2], v3 = kvp[3];
        acc[0]  = fmaf(qd, v0.x, acc[0]);  acc[1]  = fmaf(qd, v0.y, acc[1]);
        acc[2]  = fmaf(qd, v0.z, acc[2]);  acc[3]  = fmaf(qd, v0.w, acc[3]);
        acc[4]  = fmaf(qd, v1.x, acc[4]);  acc[5]  = fmaf(qd, v1.y, acc[5]);
        acc[6]  = fmaf(qd, v1.z, acc[6]);  acc[7]  = fmaf(qd, v1.w, acc[7]);
        acc[8]  = fmaf(qd, v2.x, acc[8]);  acc[9]  = fmaf(qd, v2.y, acc[9]);
        acc[10] = fmaf(qd, v2.z, acc[10]); acc[11] = fmaf(qd, v2.w, acc[11]);
        acc[12] = fmaf(qd, v3.x, acc[12]); acc[13] = fmaf(qd, v3.y, acc[13]);
        acc[14] = fmaf(qd, v3.z, acc[14]); acc[15] = fmaf(qd, v3.w, acc[15]);
    }

    float inv = 1.f / fmaxf(nrm, 1e-6f);
    const size_t idx = base + (size_t)(t0 + tl) * Dc + eb;
#pragma unroll
    for (int j = 0; j < 4; j++) {
        float a0 = acc[j * 4 + 0] * inv, a1 = acc[j * 4 + 1] * inv;
        float a2 = acc[j * 4 + 2] * inv, a3 = acc[j * 4 + 3] * inv;
        float h0 = __bfloat162float(__float2bfloat16(a0));
        float h1 = __bfloat162float(__float2bfloat16(a1));
        float h2 = __bfloat162float(__float2bfloat16(a2));
        float h3 = __bfloat162float(__float2bfloat16(a3));
        *(uint2*)(g_ah + idx + j * 4) = make_uint2(pack_bf2(a0, a1), pack_bf2(a2, a3));
        *(uint2*)(g_al + idx + j * 4) = make_uint2(pack_bf2(a0 - h0, a1 - h1),
                                                   pack_bf2(a2 - h2, a3 - h3));
    }
}

// ---------------------------------------------------------------------------
extern "C" void kernel_launch(void* const* d_in, const int* in_sizes, int n_in,
                              void* d_out, int out_size)
{
    const float* x          = (const float*)d_in[0];
    const unsigned char* mk = (const unsigned char*)d_in[1];
    const float* Ws[4] = { (const float*)d_in[2], (const float*)d_in[3],
                           (const float*)d_in[4], (const float*)d_in[5] };
    float* out              = (float*)d_out;

    float *qp, *kp, *vp;
    unsigned char* mkc;
    __nv_bfloat16 *xh, *xl, *ah, *al, *wh, *wl;
    cudaGetSymbolAddress((void**)&qp, g_q);
    cudaGetSymbolAddress((void**)&kp, g_k);
    cudaGetSymbolAddress((void**)&vp, g_v);
    cudaGetSymbolAddress((void**)&mkc, g_mask);
    cudaGetSymbolAddress((void**)&xh, g_xh);
    cudaGetSymbolAddress((void**)&xl, g_xl);
    cudaGetSymbolAddress((void**)&ah, g_ah);
    cudaGetSymbolAddress((void**)&al, g_al);
    cudaGetSymbolAddress((void**)&wh, g_wh);
    cudaGetSymbolAddress((void**)&wl, g_wl);

    cudaFuncSetAttribute(gemm_tc_kernel,
                         cudaFuncAttributeMaxDynamicSharedMemorySize, GSM_TOTAL);

    mask_convert_kernel<<<64, 256>>>(mk);
    split_kernel<<<4096, 256>>>((const float4*)x, (uint2*)xh, (uint2*)xl, BT * Dc / 4);
    for (int w = 0; w < 4; w++)
        split_kernel<<<1024, 256>>>((const float4*)Ws[w],
                                    (uint2*)(wh + (size_t)w * Dc * Dc),
                                    (uint2*)(wl + (size_t)w * Dc * Dc), Dc * Dc / 4);

    dim3 ggrid(Dc / 128, BT / 128);   // (8, 128)
    gemm_tc_kernel<<<ggrid, 256, GSM_TOTAL>>>(xh, xl, wh + 0 * (size_t)Dc * Dc, wl + 0 * (size_t)Dc * Dc, qp, mkc, 1);
    gemm_tc_kernel<<<ggrid, 256, GSM_TOTAL>>>(xh, xl, wh + 1 * (size_t)Dc * Dc, wl + 1 * (size_t)Dc * Dc, kp, mkc, 2);
    gemm_tc_kernel<<<ggrid, 256, GSM_TOTAL>>>(xh, xl, wh + 2 * (size_t)Dc * Dc, wl + 2 * (size_t)Dc * Dc, vp, mkc, 3);
    kv_partial_kernel<<<dim3(BH, SPLIT), 256>>>();
    kv_reduce_kernel<<<BH, 256>>>();
    attn_out_kernel<<<dim3(Tc / 64, BH), 256>>>();
    gemm_tc_kernel<<<ggrid, 256, GSM_TOTAL>>>(ah, al, wh + 3 * (size_t)Dc * Dc, wl + 3 * (size_t)Dc * Dc, out, mkc, 0);
}

// round 7
// speedup vs baseline: 2.0090x; 1.0273x over previous
#include <cuda_runtime.h>
#include <cuda_bf16.h>
#include <math.h>
#include <stdint.h>

// Problem constants
constexpr int Bc = 4, Tc = 4096, Dc = 1024, Hc = 16, HDc = 64;
constexpr int BT = Bc * Tc;          // 16384 rows
constexpr int BH = Bc * Hc;          // 64 (b,h) pairs
constexpr int SPLIT = 32;            // T-split for kv reduction

// Scratch (device globals: no allocation allowed in kernel_launch)
__device__ float g_q[BT * Dc];
__device__ float g_k[BT * Dc];
__device__ float g_v[BT * Dc];
__device__ float g_kvp[BH * SPLIT * HDc * HDc];
__device__ float g_ksp[BH * SPLIT * HDc];
__device__ float g_kv[BH * HDc * HDc];
__device__ float g_ksum[BH * HDc];
__device__ unsigned char g_mask[BT];
// bf16 hi/lo split operand buffers
__device__ __nv_bfloat16 g_xh[BT * Dc], g_xl[BT * Dc];
__device__ __nv_bfloat16 g_ah[BT * Dc], g_al[BT * Dc];
__device__ __nv_bfloat16 g_wh[4][Dc * Dc], g_wl[4][Dc * Dc];

__device__ __forceinline__ float phi(float x) {
    return x > 0.f ? x + 1.f : expf(x);
}

__device__ __forceinline__ uint32_t smem_u32(const void* p) {
    uint32_t a;
    asm("{ .reg .u64 t; cvta.to.shared.u64 t, %1; cvt.u32.u64 %0, t; }" : "=r"(a) : "l"(p));
    return a;
}

// pack two bf16 (from floats) into u32: x low, y high
__device__ __forceinline__ uint32_t pack_bf2(float x, float y) {
    __nv_bfloat162 h = __floats2bfloat162_rn(x, y);
    return *(uint32_t*)&h;
}

__device__ __forceinline__ void cp16(uint32_t dst, const void* src) {
    asm volatile("cp.async.cg.shared.global [%0], [%1], 16;" :: "r"(dst), "l"(src));
}
#define CP_COMMIT() asm volatile("cp.async.commit_group;" ::: "memory")
#define CP_WAIT3()  asm volatile("cp.async.wait_group 3;" ::: "memory")

// ---------------------------------------------------------------------------
// fp32 -> (hi, lo) bf16 split, vectorized
// ---------------------------------------------------------------------------
__global__ __launch_bounds__(256) void split_kernel(
    const float4* __restrict__ src, uint2* __restrict__ hi, uint2* __restrict__ lo, int n4)
{
    for (int i = blockIdx.x * 256 + threadIdx.x; i < n4; i += gridDim.x * 256) {
        float4 v = src[i];
        float hx = __bfloat162float(__float2bfloat16(v.x));
        float hy = __bfloat162float(__float2bfloat16(v.y));
        float hz = __bfloat162float(__float2bfloat16(v.z));
        float hw = __bfloat162float(__float2bfloat16(v.w));
        hi[i] = make_uint2(pack_bf2(v.x, v.y), pack_bf2(v.z, v.w));
        lo[i] = make_uint2(pack_bf2(v.x - hx, v.y - hy), pack_bf2(v.z - hz, v.w - hw));
    }
}

// all 4 weight matrices in one launch (blockIdx.y = which W)
__global__ __launch_bounds__(256) void splitw_kernel(
    const float4* __restrict__ w0, const float4* __restrict__ w1,
    const float4* __restrict__ w2, const float4* __restrict__ w3)
{
    const int wsel = blockIdx.y;
    const float4* src = wsel == 0 ? w0 : wsel == 1 ? w1 : wsel == 2 ? w2 : w3;
    uint2* hi = (uint2*)(g_wh[wsel]);
    uint2* lo = (uint2*)(g_wl[wsel]);
    const int n4 = Dc * Dc / 4;
    for (int i = blockIdx.x * 256 + threadIdx.x; i < n4; i += gridDim.x * 256) {
        float4 v = src[i];
        float hx = __bfloat162float(__float2bfloat16(v.x));
        float hy = __bfloat162float(__float2bfloat16(v.y));
        float hz = __bfloat162float(__float2bfloat16(v.z));
        float hw = __bfloat162float(__float2bfloat16(v.w));
        hi[i] = make_uint2(pack_bf2(v.x, v.y), pack_bf2(v.z, v.w));
        lo[i] = make_uint2(pack_bf2(v.x - hx, v.y - hy), pack_bf2(v.z - hz, v.w - hw));
    }
}

// ---------------------------------------------------------------------------
// 3-term bf16-split tensor-core GEMM, operands pre-split in global bf16.
// C[M,N] = A @ B^T, M=16384, N=K=1024. Tile 128x128, 8 warps (4m x 2n),
// warp tile 32x64, mma.m16n8k16.bf16, cp.async 5-stage pipeline.
// smem stage (32KB): A rows [hi 64B | lo 64B] (16KB) then B (16KB).
// op: 0 none, 1 phi, 2 phi+mask, 3 mask
// ---------------------------------------------------------------------------
constexpr int GSM_STAGE = 32768;
constexpr int NSTAGES = 5;
constexpr int GSM_TOTAL = NSTAGES * GSM_STAGE;   // 160KB

__global__ __launch_bounds__(256) void gemm_tc_kernel(
    const __nv_bfloat16* __restrict__ Ah, const __nv_bfloat16* __restrict__ Al,
    const __nv_bfloat16* __restrict__ Bh, const __nv_bfloat16* __restrict__ Bl,
    float* __restrict__ C, const unsigned char* __restrict__ mask, int op)
{
    extern __shared__ __align__(1024) char smem[];
    const uint32_t sbase = smem_u32(smem);
    const int tid = threadIdx.x;
    const int wid = tid >> 5, lane = tid & 31;
    const int wm = wid & 3, wn = wid >> 2;
    const int brow = blockIdx.y, bcol = blockIdx.x;

    // loader mapping: each thread owns (part, ci) and 4 rows r0+32i for A and B
    const int r0 = tid >> 3;            // 0..31
    const int part = (tid >> 2) & 1;    // 0 = hi, 1 = lo
    const int ci = tid & 3;             // 16B chunk within 64B half-row
    const __nv_bfloat16* srcA = (part ? Al : Ah) + (size_t)(brow * 128) * 1024;
    const __nv_bfloat16* srcB = (part ? Bl : Bh) + (size_t)(bcol * 128) * 1024;
    uint32_t dstA[4];
#pragma unroll
    for (int i = 0; i < 4; i++) {
        int row = r0 + 32 * i;
        dstA[i] = ((uint32_t)(row * 128 + part * 64 + ci * 16)) ^ (uint32_t)((row & 7) << 4);
    }

    auto load_stage = [&](int s, int buf) {
        uint32_t sb = sbase + buf * GSM_STAGE;
        const int koff = s * 32 + ci * 8;
#pragma unroll
        for (int i = 0; i < 4; i++) {
            int row = r0 + 32 * i;
            cp16(sb + dstA[i], srcA + (size_t)row * 1024 + koff);
            cp16(sb + 16384 + dstA[i], srcB + (size_t)row * 1024 + koff);
        }
    };

    // prologue: stages 0..3
#pragma unroll
    for (int s = 0; s < NSTAGES - 1; s++) {
        load_stage(s, s);
        CP_COMMIT();
    }

    float acc[2][8][4];
#pragma unroll
    for (int mt = 0; mt < 2; mt++)
#pragma unroll
        for (int nt = 0; nt < 8; nt++)
#pragma unroll
            for (int j = 0; j < 4; j++) acc[mt][nt][j] = 0.f;

    const int lrow = lane & 7;
    const int seg = lane >> 3;
    const int segr = (seg & 1) << 3;
    const int segc = (seg & 2) << 3;

    constexpr int NT = 32;
    int buf = 0;
#pragma unroll 1
    for (int t = 0; t < NT; t++) {
        CP_WAIT3();
        __syncthreads();
        if (t + NSTAGES - 1 < NT) {
            int lb = buf + NSTAGES - 1; if (lb >= NSTAGES) lb -= NSTAGES;
            load_stage(t + NSTAGES - 1, lb);
        }
        CP_COMMIT();

        const uint32_t sA = sbase + buf * GSM_STAGE;
        const uint32_t sB = sA + 16384;
        if (++buf == NSTAGES) buf = 0;

#pragma unroll
        for (int ks2 = 0; ks2 < 2; ks2++) {
            const int cH = ks2 * 32 + segc;
            const int cL = 64 + cH;

            // ---- load ALL fragments for this half-stage up front ----
            uint32_t afrH[2][4], afrL[2][4];
#pragma unroll
            for (int mt = 0; mt < 2; mt++) {
                int row = wm * 32 + mt * 16 + lrow + segr;
                uint32_t sw = (uint32_t)((row & 7) << 4);
                uint32_t oh = ((uint32_t)(row * 128 + cH)) ^ sw;
                uint32_t ol = ((uint32_t)(row * 128 + cL)) ^ sw;
                asm volatile("ldmatrix.sync.aligned.m8n8.x4.shared.b16 {%0,%1,%2,%3}, [%4];"
                    : "=r"(afrH[mt][0]), "=r"(afrH[mt][1]), "=r"(afrH[mt][2]), "=r"(afrH[mt][3])
                    : "r"(sA + oh));
                asm volatile("ldmatrix.sync.aligned.m8n8.x4.shared.b16 {%0,%1,%2,%3}, [%4];"
                    : "=r"(afrL[mt][0]), "=r"(afrL[mt][1]), "=r"(afrL[mt][2]), "=r"(afrL[mt][3])
                    : "r"(sA + ol));
            }
            uint32_t bfrH[4][4], bfrL[4][4];
#pragma unroll
            for (int nt2 = 0; nt2 < 4; nt2++) {
                int row = wn * 64 + nt2 * 16 + lrow + segr;
                uint32_t sw = (uint32_t)((row & 7) << 4);
                uint32_t oh = ((uint32_t)(row * 128 + cH)) ^ sw;
                uint32_t ol = ((uint32_t)(row * 128 + cL)) ^ sw;
                asm volatile("ldmatrix.sync.aligned.m8n8.x4.shared.b16 {%0,%1,%2,%3}, [%4];"
                    : "=r"(bfrH[nt2][0]), "=r"(bfrH[nt2][1]), "=r"(bfrH[nt2][2]), "=r"(bfrH[nt2][3])
                    : "r"(sB + oh));
                asm volatile("ldmatrix.sync.aligned.m8n8.x4.shared.b16 {%0,%1,%2,%3}, [%4];"
                    : "=r"(bfrL[nt2][0]), "=r"(bfrL[nt2][1]), "=r"(bfrL[nt2][2]), "=r"(bfrL[nt2][3])
                    : "r"(sB + ol));
            }

            // ---- 48 MMAs, no intervening smem ops ----
#pragma unroll
            for (int mt = 0; mt < 2; mt++)
#pragma unroll
                for (int nt = 0; nt < 8; nt++) {
                    const int g = nt >> 1, h = nt & 1;
                    asm volatile(
                        "mma.sync.aligned.m16n8k16.row.col.f32.bf16.bf16.f32 "
                        "{%0,%1,%2,%3}, {%4,%5,%6,%7}, {%8,%9}, {%0,%1,%2,%3};"
                        : "+f"(acc[mt][nt][0]), "+f"(acc[mt][nt][1]),
                          "+f"(acc[mt][nt][2]), "+f"(acc[mt][nt][3])
                        : "r"(afrH[mt][0]), "r"(afrH[mt][1]), "r"(afrH[mt][2]), "r"(afrH[mt][3]),
                          "r"(bfrH[g][h]), "r"(bfrH[g][h + 2]));
                    asm volatile(
                        "mma.sync.aligned.m16n8k16.row.col.f32.bf16.bf16.f32 "
                        "{%0,%1,%2,%3}, {%4,%5,%6,%7}, {%8,%9}, {%0,%1,%2,%3};"
                        : "+f"(acc[mt][nt][0]), "+f"(acc[mt][nt][1]),
                          "+f"(acc[mt][nt][2]), "+f"(acc[mt][nt][3])
                        : "r"(afrL[mt][0]), "r"(afrL[mt][1]), "r"(afrL[mt][2]), "r"(afrL[mt][3]),
                          "r"(bfrH[g][h]), "r"(bfrH[g][h + 2]));
                    asm volatile(
                        "mma.sync.aligned.m16n8k16.row.col.f32.bf16.bf16.f32 "
                        "{%0,%1,%2,%3}, {%4,%5,%6,%7}, {%8,%9}, {%0,%1,%2,%3};"
                        : "+f"(acc[mt][nt][0]), "+f"(acc[mt][nt][1]),
                          "+f"(acc[mt][nt][2]), "+f"(acc[mt][nt][3])
                        : "r"(afrH[mt][0]), "r"(afrH[mt][1]), "r"(afrH[mt][2]), "r"(afrH[mt][3]),
                          "r"(bfrL[g][h]), "r"(bfrL[g][h + 2]));
                }
        }
    }

    // Epilogue
    const int r0e = brow * 128 + wm * 32 + (lane >> 2);
    const int c0 = bcol * 128 + wn * 64 + (lane & 3) * 2;
    const bool do_phi = (op == 1 || op == 2);
    const bool do_msk = (op >= 2);
#pragma unroll
    for (int mt = 0; mt < 2; mt++) {
        const int r = r0e + mt * 16;
        const bool mz0 = do_msk && (mask[r] != 0);
        const bool mz1 = do_msk && (mask[r + 8] != 0);
#pragma unroll
        for (int nt = 0; nt < 8; nt++) {
            float2 v0 = make_float2(acc[mt][nt][0], acc[mt][nt][1]);
            float2 v1 = make_float2(acc[mt][nt][2], acc[mt][nt][3]);
            if (do_phi) {
                v0.x = phi(v0.x); v0.y = phi(v0.y);
                v1.x = phi(v1.x); v1.y = phi(v1.y);
            }
            if (mz0) { v0.x = 0.f; v0.y = 0.f; }
            if (mz1) { v1.x = 0.f; v1.y = 0.f; }
            *(float2*)(C + (size_t)r * 1024 + c0 + nt * 8) = v0;
            *(float2*)(C + (size_t)(r + 8) * 1024 + c0 + nt * 8) = v1;
        }
    }
}

// ---------------------------------------------------------------------------
// Mask normalization (dtype-agnostic) -> uint8 0/1
// ---------------------------------------------------------------------------
__global__ __launch_bounds__(256) void mask_convert_kernel(const unsigned char* __restrict__ mraw)
{
    __shared__ int s_float, s_odd;
    if (threadIdx.x == 0) { s_float = 0; s_odd = 0; }
    __syncthreads();
    for (int i = threadIdx.x; i < 4096; i += 256) {
        unsigned char v = mraw[i];
        if (v == 0x3F) s_float = 1;
        if (v != 0 && (i & 3) != 0) s_odd = 1;
    }
    __syncthreads();
    const int dtype = s_float ? 2 : (s_odd ? 0 : 1);

    const int m0 = blockIdx.x * 256 + threadIdx.x;
    for (int m = m0; m < BT; m += 64 * 256) {
        unsigned char r;
        if (dtype == 0)      r = (mraw[m] != 0);
        else if (dtype == 1) r = (((const int*)mraw)[m] != 0);
        else                 r = (((const float*)mraw)[m] != 0.0f);
        g_mask[m] = r;
    }
}

// ---------------------------------------------------------------------------
// kv partial: for (b,h,split): kv[d][e] += k[t,d]*v[t,e]; ksum[d] += k[t,d]
// grid (BH, SPLIT), 256 threads
// ---------------------------------------------------------------------------
__global__ __launch_bounds__(256) void kv_partial_kernel()
{
    const int tid = threadIdx.x;
    const int bh = blockIdx.x, sy = blockIdx.y;
    const int b = bh >> 4, h = bh & 15;
    const int t0 = sy * (Tc / SPLIT);

    __shared__ __align__(16) float Ks[32][64];
    __shared__ __align__(16) float Vs[32][64];

    float acc[16];
#pragma unroll
    for (int j = 0; j < 16; j++) acc[j] = 0.f;
    float ks = 0.f;

    const int d = tid >> 2;
    const int eb = (tid & 3) * 16;
    const size_t base = ((size_t)b * Tc) * Dc + h * 64;

    for (int tc = 0; tc < Tc / SPLIT; tc += 32) {
#pragma unroll
        for (int it = 0; it < 2; it++) {
            int i = tid + it * 256;
            int tl = i >> 4;
            int c4 = (i & 15) * 4;
            size_t off = base + (size_t)(t0 + tc + tl) * Dc + c4;
            *(float4*)&Ks[tl][c4] = *(const float4*)(g_k + off);
            *(float4*)&Vs[tl][c4] = *(const float4*)(g_v + off);
        }
        __syncthreads();
#pragma unroll
        for (int t = 0; t < 32; t++) {
            float kd = Ks[t][d];
            ks += kd;
            float4 v0 = *(const float4*)&Vs[t][eb];
            float4 v1 = *(const float4*)&Vs[t][eb + 4];
            float4 v2 = *(const float4*)&Vs[t][eb + 8];
            float4 v3 = *(const float4*)&Vs[t][eb + 12];
            acc[0]  = fmaf(kd, v0.x, acc[0]);  acc[1]  = fmaf(kd, v0.y, acc[1]);
            acc[2]  = fmaf(kd, v0.z, acc[2]);  acc[3]  = fmaf(kd, v0.w, acc[3]);
            acc[4]  = fmaf(kd, v1.x, acc[4]);  acc[5]  = fmaf(kd, v1.y, acc[5]);
            acc[6]  = fmaf(kd, v1.z, acc[6]);  acc[7]  = fmaf(kd, v1.w, acc[7]);
            acc[8]  = fmaf(kd, v2.x, acc[8]);  acc[9]  = fmaf(kd, v2.y, acc[9]);
            acc[10] = fmaf(kd, v2.z, acc[10]); acc[11] = fmaf(kd, v2.w, acc[11]);
            acc[12] = fmaf(kd, v3.x, acc[12]); acc[13] = fmaf(kd, v3.y, acc[13]);
            acc[14] = fmaf(kd, v3.z, acc[14]); acc[15] = fmaf(kd, v3.w, acc[15]);
        }
        __syncthreads();
    }

    float* outp = g_kvp + ((size_t)(bh * SPLIT + sy)) * 4096 + d * 64 + eb;
    *(float4*)(outp + 0)  = make_float4(acc[0], acc[1], acc[2], acc[3]);
    *(float4*)(outp + 4)  = make_float4(acc[4], acc[5], acc[6], acc[7]);
    *(float4*)(outp + 8)  = make_float4(acc[8], acc[9], acc[10], acc[11]);
    *(float4*)(outp + 12) = make_float4(acc[12], acc[13], acc[14], acc[15]);
    if ((tid & 3) == 0)
        g_ksp[(bh * SPLIT + sy) * 64 + d] = ks;
}

// ---------------------------------------------------------------------------
__global__ __launch_bounds__(256) void kv_reduce_kernel()
{
    const int bh = blockIdx.x, tid = threadIdx.x;
#pragma unroll
    for (int j = 0; j < 4; j++) {
        int off = tid * 16 + j * 4;
        float4 s = make_float4(0.f, 0.f, 0.f, 0.f);
#pragma unroll
        for (int sp = 0; sp < SPLIT; sp++) {
            float4 p = *(const float4*)(g_kvp + ((size_t)(bh * SPLIT + sp)) * 4096 + off);
            s.x += p.x; s.y += p.y; s.z += p.z; s.w += p.w;
        }
        *(float4*)(g_kv + (size_t)bh * 4096 + off) = s;
    }
    if (tid < 64) {
        float s = 0.f;
#pragma unroll
        for (int sp = 0; sp < SPLIT; sp++)
            s += g_ksp[(bh * SPLIT + sp) * 64 + tid];
        g_ksum[bh * 64 + tid] = s;
    }
}

// ---------------------------------------------------------------------------
// attn out: out[t,e] = (sum_d q[t,d]*kv[d,e]) / max(q[t]·ksum, 1e-6)
// Writes bf16 hi/lo split directly (input of the final GEMM).
// ---------------------------------------------------------------------------
__global__ __launch_bounds__(256) void attn_out_kernel()
{
    const int tid = threadIdx.x;
    const int bh = blockIdx.y;
    const int b = bh >> 4, h = bh & 15;
    const int t0 = blockIdx.x * 64;

    __shared__ __align__(16) float KV[4096];
    __shared__ float Qs[64][65];
    __shared__ float Ksm[64];

#pragma unroll
    for (int j = 0; j < 4; j++) {
        int f = tid + j * 256;
        *(float4*)&KV[f * 4] = *(const float4*)(g_kv + (size_t)bh * 4096 + f * 4);
    }
    if (tid < 64) Ksm[tid] = g_ksum[bh * 64 + tid];

    const size_t base = ((size_t)b * Tc) * Dc + h * 64;
#pragma unroll
    for (int j = 0; j < 16; j++) {
        int i = tid + j * 256;
        int tl = i >> 6, d = i & 63;
        Qs[d][tl] = g_q[base + (size_t)(t0 + tl) * Dc + d];
    }
    __syncthreads();

    const int tl = tid >> 2;
    const int eb = (tid & 3) * 16;
    float acc[16];
#pragma unroll
    for (int j = 0; j < 16; j++) acc[j] = 0.f;
    float nrm = 0.f;

#pragma unroll
    for (int d2 = 0; d2 < 64; d2++) {
        float qd = Qs[d2][tl];
        nrm = fmaf(qd, Ksm[d2], nrm);
        const float4* kvp = (const float4*)&KV[d2 * 64 + eb];
        float4 v0 = kvp[0], v1 = kvp[1], v2 = kvp[2], v3 = kvp[3];
        acc[0]  = fmaf(qd, v0.x, acc[0]);  acc[1]  = fmaf(qd, v0.y, acc[1]);
        acc[2]  = fmaf(qd, v0.z, acc[2]);  acc[3]  = fmaf(qd, v0.w, acc[3]);
        acc[4]  = fmaf(qd, v1.x, acc[4]);  acc[5]  = fmaf(qd, v1.y, acc[5]);
        acc[6]  = fmaf(qd, v1.z, acc[6]);  acc[7]  = fmaf(qd, v1.w, acc[7]);
        acc[8]  = fmaf(qd, v2.x, acc[8]);  acc[9]  = fmaf(qd, v2.y, acc[9]);
        acc[10] = fmaf(qd, v2.z, acc[10]); acc[11] = fmaf(qd, v2.w, acc[11]);
        acc[12] = fmaf(qd, v3.x, acc[12]); acc[13] = fmaf(qd, v3.y, acc[13]);
        acc[14] = fmaf(qd, v3.z, acc[14]); acc[15] = fmaf(qd, v3.w, acc[15]);
    }

    float inv = 1.f / fmaxf(nrm, 1e-6f);
    const size_t idx = base + (size_t)(t0 + tl) * Dc + eb;
#pragma unroll
    for (int j = 0; j < 4; j++) {
        float a0 = acc[j * 4 + 0] * inv, a1 = acc[j * 4 + 1] * inv;
        float a2 = acc[j * 4 + 2] * inv, a3 = acc[j * 4 + 3] * inv;
        float h0 = __bfloat162float(__float2bfloat16(a0));
        float h1 = __bfloat162float(__float2bfloat16(a1));
        float h2 = __bfloat162float(__float2bfloat16(a2));
        float h3 = __bfloat162float(__float2bfloat16(a3));
        *(uint2*)(g_ah + idx + j * 4) = make_uint2(pack_bf2(a0, a1), pack_bf2(a2, a3));
        *(uint2*)(g_al + idx + j * 4) = make_uint2(pack_bf2(a0 - h0, a1 - h1),
                                                   pack_bf2(a2 - h2, a3 - h3));
    }
}

// ---------------------------------------------------------------------------
extern "C" void kernel_launch(void* const* d_in, const int* in_sizes, int n_in,
                              void* d_out, int out_size)
{
    const float* x          = (const float*)d_in[0];
    const unsigned char* mk = (const unsigned char*)d_in[1];
    float* out              = (float*)d_out;

    float *qp, *kp, *vp;
    unsigned char* mkc;
    __nv_bfloat16 *xh, *xl, *ah, *al, *wh, *wl;
    cudaGetSymbolAddress((void**)&qp, g_q);
    cudaGetSymbolAddress((void**)&kp, g_k);
    cudaGetSymbolAddress((void**)&vp, g_v);
    cudaGetSymbolAddress((void**)&mkc, g_mask);
    cudaGetSymbolAddress((void**)&xh, g_xh);
    cudaGetSymbolAddress((void**)&xl, g_xl);
    cudaGetSymbolAddress((void**)&ah, g_ah);
    cudaGetSymbolAddress((void**)&al, g_al);
    cudaGetSymbolAddress((void**)&wh, g_wh);
    cudaGetSymbolAddress((void**)&wl, g_wl);

    cudaFuncSetAttribute(gemm_tc_kernel,
                         cudaFuncAttributeMaxDynamicSharedMemorySize, GSM_TOTAL);

    // Launch order chosen so ncu (-s 5 -c 1) profiles a GEMM (6th launch).
    split_kernel<<<4096, 256>>>((const float4*)x, (uint2*)xh, (uint2*)xl, BT * Dc / 4);      // 1
    splitw_kernel<<<dim3(512, 4), 256>>>((const float4*)d_in[2], (const float4*)d_in[3],
                                         (const float4*)d_in[4], (const float4*)d_in[5]);    // 2
    mask_convert_kernel<<<64, 256>>>(mk);                                                    // 3

    dim3 ggrid(Dc / 128, BT / 128);   // (8, 128)
    gemm_tc_kernel<<<ggrid, 256, GSM_TOTAL>>>(xh, xl, wh + 0 * (size_t)Dc * Dc, wl + 0 * (size_t)Dc * Dc, qp, mkc, 1);  // 4
    gemm_tc_kernel<<<ggrid, 256, GSM_TOTAL>>>(xh, xl, wh + 1 * (size_t)Dc * Dc, wl + 1 * (size_t)Dc * Dc, kp, mkc, 2);  // 5
    gemm_tc_kernel<<<ggrid, 256, GSM_TOTAL>>>(xh, xl, wh + 2 * (size_t)Dc * Dc, wl + 2 * (size_t)Dc * Dc, vp, mkc, 3);  // 6 <- profiled
    kv_partial_kernel<<<dim3(BH, SPLIT), 256>>>();
    kv_reduce_kernel<<<BH, 256>>>();
    attn_out_kernel<<<dim3(Tc / 64, BH), 256>>>();
    gemm_tc_kernel<<<ggrid, 256, GSM_TOTAL>>>(ah, al, wh + 3 * (size_t)Dc * Dc, wl + 3 * (size_t)Dc * Dc, out, mkc, 0);
}

// round 8
// speedup vs baseline: 2.1411x; 1.0658x over previous
#include <cuda_runtime.h>
#include <cuda_bf16.h>
#include <math.h>
#include <stdint.h>

// Problem constants
constexpr int Bc = 4, Tc = 4096, Dc = 1024, Hc = 16, HDc = 64;
constexpr int BT = Bc * Tc;          // 16384 rows
constexpr int BH = Bc * Hc;          // 64 (b,h) pairs
constexpr int SPLIT = 32;            // T-split for kv reduction

// Scratch (device globals: no allocation allowed in kernel_launch)
__device__ float g_q[BT * Dc];
__device__ float g_k[BT * Dc];
__device__ float g_v[BT * Dc];
__device__ float g_kvp[BH * SPLIT * HDc * HDc];
__device__ float g_ksp[BH * SPLIT * HDc];
__device__ float g_kv[BH * HDc * HDc];
__device__ float g_ksum[BH * HDc];
__device__ unsigned char g_mask[BT];
// bf16 hi/lo split operand buffers
__device__ __nv_bfloat16 g_xh[BT * Dc], g_xl[BT * Dc];
__device__ __nv_bfloat16 g_ah[BT * Dc], g_al[BT * Dc];
__device__ __nv_bfloat16 g_wh[4][Dc * Dc], g_wl[4][Dc * Dc];

__device__ __forceinline__ float phi(float x) {
    return x > 0.f ? x + 1.f : expf(x);
}

__device__ __forceinline__ uint32_t smem_u32(const void* p) {
    uint32_t a;
    asm("{ .reg .u64 t; cvta.to.shared.u64 t, %1; cvt.u32.u64 %0, t; }" : "=r"(a) : "l"(p));
    return a;
}

// pack two bf16 (from floats) into u32: x low, y high
__device__ __forceinline__ uint32_t pack_bf2(float x, float y) {
    __nv_bfloat162 h = __floats2bfloat162_rn(x, y);
    return *(uint32_t*)&h;
}

__device__ __forceinline__ void cp16(uint32_t dst, const void* src) {
    asm volatile("cp.async.cg.shared.global [%0], [%1], 16;" :: "r"(dst), "l"(src));
}
#define CP_COMMIT() asm volatile("cp.async.commit_group;" ::: "memory")
#define CP_WAIT1()  asm volatile("cp.async.wait_group 1;" ::: "memory")

// ---------------------------------------------------------------------------
// fp32 -> (hi, lo) bf16 split, vectorized
// ---------------------------------------------------------------------------
__global__ __launch_bounds__(256) void split_kernel(
    const float4* __restrict__ src, uint2* __restrict__ hi, uint2* __restrict__ lo, int n4)
{
    for (int i = blockIdx.x * 256 + threadIdx.x; i < n4; i += gridDim.x * 256) {
        float4 v = src[i];
        float hx = __bfloat162float(__float2bfloat16(v.x));
        float hy = __bfloat162float(__float2bfloat16(v.y));
        float hz = __bfloat162float(__float2bfloat16(v.z));
        float hw = __bfloat162float(__float2bfloat16(v.w));
        hi[i] = make_uint2(pack_bf2(v.x, v.y), pack_bf2(v.z, v.w));
        lo[i] = make_uint2(pack_bf2(v.x - hx, v.y - hy), pack_bf2(v.z - hz, v.w - hw));
    }
}

// all 4 weight matrices in one launch (blockIdx.y = which W)
__global__ __launch_bounds__(256) void splitw_kernel(
    const float4* __restrict__ w0, const float4* __restrict__ w1,
    const float4* __restrict__ w2, const float4* __restrict__ w3)
{
    const int wsel = blockIdx.y;
    const float4* src = wsel == 0 ? w0 : wsel == 1 ? w1 : wsel == 2 ? w2 : w3;
    uint2* hi = (uint2*)(g_wh[wsel]);
    uint2* lo = (uint2*)(g_wl[wsel]);
    const int n4 = Dc * Dc / 4;
    for (int i = blockIdx.x * 256 + threadIdx.x; i < n4; i += gridDim.x * 256) {
        float4 v = src[i];
        float hx = __bfloat162float(__float2bfloat16(v.x));
        float hy = __bfloat162float(__float2bfloat16(v.y));
        float hz = __bfloat162float(__float2bfloat16(v.z));
        float hw = __bfloat162float(__float2bfloat16(v.w));
        hi[i] = make_uint2(pack_bf2(v.x, v.y), pack_bf2(v.z, v.w));
        lo[i] = make_uint2(pack_bf2(v.x - hx, v.y - hy), pack_bf2(v.z - hz, v.w - hw));
    }
}

// ---------------------------------------------------------------------------
// 3-term bf16-split tensor-core GEMM, operands pre-split in global bf16.
// C[M,N] = A @ B^T, M=16384, N=K=1024. Tile 128x128, 8 warps (4m x 2n),
// warp tile 32x64, mma.m16n8k16.bf16, cp.async 3-stage pipeline, 2 CTAs/SM.
// smem stage (32KB): A rows [hi 64B | lo 64B] (16KB) then B (16KB).
// op: 0 none, 1 phi, 2 phi+mask, 3 mask
// ---------------------------------------------------------------------------
constexpr int GSM_STAGE = 32768;
constexpr int NSTAGES = 3;
constexpr int GSM_TOTAL = NSTAGES * GSM_STAGE;   // 96KB -> 2 CTAs/SM

__global__ __launch_bounds__(256, 2) void gemm_tc_kernel(
    const __nv_bfloat16* __restrict__ Ah, const __nv_bfloat16* __restrict__ Al,
    const __nv_bfloat16* __restrict__ Bh, const __nv_bfloat16* __restrict__ Bl,
    float* __restrict__ C, const unsigned char* __restrict__ mask, int op)
{
    extern __shared__ __align__(1024) char smem[];
    const uint32_t sbase = smem_u32(smem);
    const int tid = threadIdx.x;
    const int wid = tid >> 5, lane = tid & 31;
    const int wm = wid & 3, wn = wid >> 2;
    const int brow = blockIdx.y, bcol = blockIdx.x;

    // loader mapping: each thread owns (part, ci) and 4 rows r0+32i for A and B
    const int r0 = tid >> 3;            // 0..31
    const int part = (tid >> 2) & 1;    // 0 = hi, 1 = lo
    const int ci = tid & 3;             // 16B chunk within 64B half-row
    const __nv_bfloat16* srcA = (part ? Al : Ah) + (size_t)(brow * 128) * 1024;
    const __nv_bfloat16* srcB = (part ? Bl : Bh) + (size_t)(bcol * 128) * 1024;
    uint32_t dstA[4];
#pragma unroll
    for (int i = 0; i < 4; i++) {
        int row = r0 + 32 * i;
        dstA[i] = ((uint32_t)(row * 128 + part * 64 + ci * 16)) ^ (uint32_t)((row & 7) << 4);
    }

    auto load_stage = [&](int s, int buf) {
        uint32_t sb = sbase + buf * GSM_STAGE;
        const int koff = s * 32 + ci * 8;
#pragma unroll
        for (int i = 0; i < 4; i++) {
            int row = r0 + 32 * i;
            cp16(sb + dstA[i], srcA + (size_t)row * 1024 + koff);
            cp16(sb + 16384 + dstA[i], srcB + (size_t)row * 1024 + koff);
        }
    };

    // prologue: stages 0..1
#pragma unroll
    for (int s = 0; s < NSTAGES - 1; s++) {
        load_stage(s, s);
        CP_COMMIT();
    }

    float acc[2][8][4];
#pragma unroll
    for (int mt = 0; mt < 2; mt++)
#pragma unroll
        for (int nt = 0; nt < 8; nt++)
#pragma unroll
            for (int j = 0; j < 4; j++) acc[mt][nt][j] = 0.f;

    const int lrow = lane & 7;
    const int seg = lane >> 3;
    const int segr = (seg & 1) << 3;
    const int segc = (seg & 2) << 3;

    constexpr int NT = 32;
    int buf = 0;
#pragma unroll 1
    for (int t = 0; t < NT; t++) {
        CP_WAIT1();
        __syncthreads();
        if (t + NSTAGES - 1 < NT) {
            int lb = buf + NSTAGES - 1; if (lb >= NSTAGES) lb -= NSTAGES;
            load_stage(t + NSTAGES - 1, lb);
        }
        CP_COMMIT();

        const uint32_t sA = sbase + buf * GSM_STAGE;
        const uint32_t sB = sA + 16384;
        if (++buf == NSTAGES) buf = 0;

#pragma unroll
        for (int ks2 = 0; ks2 < 2; ks2++) {
            const int cH = ks2 * 32 + segc;
            const int cL = 64 + cH;

            // ---- load ALL fragments for this half-stage up front ----
            uint32_t afrH[2][4], afrL[2][4];
#pragma unroll
            for (int mt = 0; mt < 2; mt++) {
                int row = wm * 32 + mt * 16 + lrow + segr;
                uint32_t sw = (uint32_t)((row & 7) << 4);
                uint32_t oh = ((uint32_t)(row * 128 + cH)) ^ sw;
                uint32_t ol = ((uint32_t)(row * 128 + cL)) ^ sw;
                asm volatile("ldmatrix.sync.aligned.m8n8.x4.shared.b16 {%0,%1,%2,%3}, [%4];"
                    : "=r"(afrH[mt][0]), "=r"(afrH[mt][1]), "=r"(afrH[mt][2]), "=r"(afrH[mt][3])
                    : "r"(sA + oh));
                asm volatile("ldmatrix.sync.aligned.m8n8.x4.shared.b16 {%0,%1,%2,%3}, [%4];"
                    : "=r"(afrL[mt][0]), "=r"(afrL[mt][1]), "=r"(afrL[mt][2]), "=r"(afrL[mt][3])
                    : "r"(sA + ol));
            }
            uint32_t bfrH[4][4], bfrL[4][4];
#pragma unroll
            for (int nt2 = 0; nt2 < 4; nt2++) {
                int row = wn * 64 + nt2 * 16 + lrow + segr;
                uint32_t sw = (uint32_t)((row & 7) << 4);
                uint32_t oh = ((uint32_t)(row * 128 + cH)) ^ sw;
                uint32_t ol = ((uint32_t)(row * 128 + cL)) ^ sw;
                asm volatile("ldmatrix.sync.aligned.m8n8.x4.shared.b16 {%0,%1,%2,%3}, [%4];"
                    : "=r"(bfrH[nt2][0]), "=r"(bfrH[nt2][1]), "=r"(bfrH[nt2][2]), "=r"(bfrH[nt2][3])
                    : "r"(sB + oh));
                asm volatile("ldmatrix.sync.aligned.m8n8.x4.shared.b16 {%0,%1,%2,%3}, [%4];"
                    : "=r"(bfrL[nt2][0]), "=r"(bfrL[nt2][1]), "=r"(bfrL[nt2][2]), "=r"(bfrL[nt2][3])
                    : "r"(sB + ol));
            }

            // ---- 48 MMAs, no intervening smem ops ----
#pragma unroll
            for (int mt = 0; mt < 2; mt++)
#pragma unroll
                for (int nt = 0; nt < 8; nt++) {
                    const int g = nt >> 1, h = nt & 1;
                    asm volatile(
                        "mma.sync.aligned.m16n8k16.row.col.f32.bf16.bf16.f32 "
                        "{%0,%1,%2,%3}, {%4,%5,%6,%7}, {%8,%9}, {%0,%1,%2,%3};"
                        : "+f"(acc[mt][nt][0]), "+f"(acc[mt][nt][1]),
                          "+f"(acc[mt][nt][2]), "+f"(acc[mt][nt][3])
                        : "r"(afrH[mt][0]), "r"(afrH[mt][1]), "r"(afrH[mt][2]), "r"(afrH[mt][3]),
                          "r"(bfrH[g][h]), "r"(bfrH[g][h + 2]));
                    asm volatile(
                        "mma.sync.aligned.m16n8k16.row.col.f32.bf16.bf16.f32 "
                        "{%0,%1,%2,%3}, {%4,%5,%6,%7}, {%8,%9}, {%0,%1,%2,%3};"
                        : "+f"(acc[mt][nt][0]), "+f"(acc[mt][nt][1]),
                          "+f"(acc[mt][nt][2]), "+f"(acc[mt][nt][3])
                        : "r"(afrL[mt][0]), "r"(afrL[mt][1]), "r"(afrL[mt][2]), "r"(afrL[mt][3]),
                          "r"(bfrH[g][h]), "r"(bfrH[g][h + 2]));
                    asm volatile(
                        "mma.sync.aligned.m16n8k16.row.col.f32.bf16.bf16.f32 "
                        "{%0,%1,%2,%3}, {%4,%5,%6,%7}, {%8,%9}, {%0,%1,%2,%3};"
                        : "+f"(acc[mt][nt][0]), "+f"(acc[mt][nt][1]),
                          "+f"(acc[mt][nt][2]), "+f"(acc[mt][nt][3])
                        : "r"(afrH[mt][0]), "r"(afrH[mt][1]), "r"(afrH[mt][2]), "r"(afrH[mt][3]),
                          "r"(bfrL[g][h]), "r"(bfrL[g][h + 2]));
                }
        }
    }

    // Epilogue
    const int r0e = brow * 128 + wm * 32 + (lane >> 2);
    const int c0 = bcol * 128 + wn * 64 + (lane & 3) * 2;
    const bool do_phi = (op == 1 || op == 2);
    const bool do_msk = (op >= 2);
#pragma unroll
    for (int mt = 0; mt < 2; mt++) {
        const int r = r0e + mt * 16;
        const bool mz0 = do_msk && (mask[r] != 0);
        const bool mz1 = do_msk && (mask[r + 8] != 0);
#pragma unroll
        for (int nt = 0; nt < 8; nt++) {
            float2 v0 = make_float2(acc[mt][nt][0], acc[mt][nt][1]);
            float2 v1 = make_float2(acc[mt][nt][2], acc[mt][nt][3]);
            if (do_phi) {
                v0.x = phi(v0.x); v0.y = phi(v0.y);
                v1.x = phi(v1.x); v1.y = phi(v1.y);
            }
            if (mz0) { v0.x = 0.f; v0.y = 0.f; }
            if (mz1) { v1.x = 0.f; v1.y = 0.f; }
            *(float2*)(C + (size_t)r * 1024 + c0 + nt * 8) = v0;
            *(float2*)(C + (size_t)(r + 8) * 1024 + c0 + nt * 8) = v1;
        }
    }
}

// ---------------------------------------------------------------------------
// Mask normalization (dtype-agnostic) -> uint8 0/1
// ---------------------------------------------------------------------------
__global__ __launch_bounds__(256) void mask_convert_kernel(const unsigned char* __restrict__ mraw)
{
    __shared__ int s_float, s_odd;
    if (threadIdx.x == 0) { s_float = 0; s_odd = 0; }
    __syncthreads();
    for (int i = threadIdx.x; i < 4096; i += 256) {
        unsigned char v = mraw[i];
        if (v == 0x3F) s_float = 1;
        if (v != 0 && (i & 3) != 0) s_odd = 1;
    }
    __syncthreads();
    const int dtype = s_float ? 2 : (s_odd ? 0 : 1);

    const int m0 = blockIdx.x * 256 + threadIdx.x;
    for (int m = m0; m < BT; m += 64 * 256) {
        unsigned char r;
        if (dtype == 0)      r = (mraw[m] != 0);
        else if (dtype == 1) r = (((const int*)mraw)[m] != 0);
        else                 r = (((const float*)mraw)[m] != 0.0f);
        g_mask[m] = r;
    }
}

// ---------------------------------------------------------------------------
// kv partial: for (b,h,split): kv[d][e] += k[t,d]*v[t,e]; ksum[d] += k[t,d]
// grid (BH, SPLIT), 256 threads
// ---------------------------------------------------------------------------
__global__ __launch_bounds__(256) void kv_partial_kernel()
{
    const int tid = threadIdx.x;
    const int bh = blockIdx.x, sy = blockIdx.y;
    const int b = bh >> 4, h = bh & 15;
    const int t0 = sy * (Tc / SPLIT);

    __shared__ __align__(16) float Ks[32][64];
    __shared__ __align__(16) float Vs[32][64];

    float acc[16];
#pragma unroll
    for (int j = 0; j < 16; j++) acc[j] = 0.f;
    float ks = 0.f;

    const int d = tid >> 2;
    const int eb = (tid & 3) * 16;
    const size_t base = ((size_t)b * Tc) * Dc + h * 64;

    for (int tc = 0; tc < Tc / SPLIT; tc += 32) {
#pragma unroll
        for (int it = 0; it < 2; it++) {
            int i = tid + it * 256;
            int tl = i >> 4;
            int c4 = (i & 15) * 4;
            size_t off = base + (size_t)(t0 + tc + tl) * Dc + c4;
            *(float4*)&Ks[tl][c4] = *(const float4*)(g_k + off);
            *(float4*)&Vs[tl][c4] = *(const float4*)(g_v + off);
        }
        __syncthreads();
#pragma unroll
        for (int t = 0; t < 32; t++) {
            float kd = Ks[t][d];
            ks += kd;
            float4 v0 = *(const float4*)&Vs[t][eb];
            float4 v1 = *(const float4*)&Vs[t][eb + 4];
            float4 v2 = *(const float4*)&Vs[t][eb + 8];
            float4 v3 = *(const float4*)&Vs[t][eb + 12];
            acc[0]  = fmaf(kd, v0.x, acc[0]);  acc[1]  = fmaf(kd, v0.y, acc[1]);
            acc[2]  = fmaf(kd, v0.z, acc[2]);  acc[3]  = fmaf(kd, v0.w, acc[3]);
            acc[4]  = fmaf(kd, v1.x, acc[4]);  acc[5]  = fmaf(kd, v1.y, acc[5]);
            acc[6]  = fmaf(kd, v1.z, acc[6]);  acc[7]  = fmaf(kd, v1.w, acc[7]);
            acc[8]  = fmaf(kd, v2.x, acc[8]);  acc[9]  = fmaf(kd, v2.y, acc[9]);
            acc[10] = fmaf(kd, v2.z, acc[10]); acc[11] = fmaf(kd, v2.w, acc[11]);
            acc[12] = fmaf(kd, v3.x, acc[12]); acc[13] = fmaf(kd, v3.y, acc[13]);
            acc[14] = fmaf(kd, v3.z, acc[14]); acc[15] = fmaf(kd, v3.w, acc[15]);
        }
        __syncthreads();
    }

    float* outp = g_kvp + ((size_t)(bh * SPLIT + sy)) * 4096 + d * 64 + eb;
    *(float4*)(outp + 0)  = make_float4(acc[0], acc[1], acc[2], acc[3]);
    *(float4*)(outp + 4)  = make_float4(acc[4], acc[5], acc[6], acc[7]);
    *(float4*)(outp + 8)  = make_float4(acc[8], acc[9], acc[10], acc[11]);
    *(float4*)(outp + 12) = make_float4(acc[12], acc[13], acc[14], acc[15]);
    if ((tid & 3) == 0)
        g_ksp[(bh * SPLIT + sy) * 64 + d] = ks;
}

// ---------------------------------------------------------------------------
__global__ __launch_bounds__(256) void kv_reduce_kernel()
{
    const int bh = blockIdx.x, tid = threadIdx.x;
#pragma unroll
    for (int j = 0; j < 4; j++) {
        int off = tid * 16 + j * 4;
        float4 s = make_float4(0.f, 0.f, 0.f, 0.f);
#pragma unroll
        for (int sp = 0; sp < SPLIT; sp++) {
            float4 p = *(const float4*)(g_kvp + ((size_t)(bh * SPLIT + sp)) * 4096 + off);
            s.x += p.x; s.y += p.y; s.z += p.z; s.w += p.w;
        }
        *(float4*)(g_kv + (size_t)bh * 4096 + off) = s;
    }
    if (tid < 64) {
        float s = 0.f;
#pragma unroll
        for (int sp = 0; sp < SPLIT; sp++)
            s += g_ksp[(bh * SPLIT + sp) * 64 + tid];
        g_ksum[bh * 64 + tid] = s;
    }
}

// ---------------------------------------------------------------------------
// attn out: out[t,e] = (sum_d q[t,d]*kv[d,e]) / max(q[t]·ksum, 1e-6)
// Writes bf16 hi/lo split directly (input of the final GEMM).
// ---------------------------------------------------------------------------
__global__ __launch_bounds__(256) void attn_out_kernel()
{
    const int tid = threadIdx.x;
    const int bh = blockIdx.y;
    const int b = bh >> 4, h = bh & 15;
    const int t0 = blockIdx.x * 64;

    __shared__ __align__(16) float KV[4096];
    __shared__ float Qs[64][65];
    __shared__ float Ksm[64];

#pragma unroll
    for (int j = 0; j < 4; j++) {
        int f = tid + j * 256;
        *(float4*)&KV[f * 4] = *(const float4*)(g_kv + (size_t)bh * 4096 + f * 4);
    }
    if (tid < 64) Ksm[tid] = g_ksum[bh * 64 + tid];

    const size_t base = ((size_t)b * Tc) * Dc + h * 64;
#pragma unroll
    for (int j = 0; j < 16; j++) {
        int i = tid + j * 256;
        int tl = i >> 6, d = i & 63;
        Qs[d][tl] = g_q[base + (size_t)(t0 + tl) * Dc + d];
    }
    __syncthreads();

    const int tl = tid >> 2;
    const int eb = (tid & 3) * 16;
    float acc[16];
#pragma unroll
    for (int j = 0; j < 16; j++) acc[j] = 0.f;
    float nrm = 0.f;

#pragma unroll
    for (int d2 = 0; d2 < 64; d2++) {
        float qd = Qs[d2][tl];
        nrm = fmaf(qd, Ksm[d2], nrm);
        const float4* kvp = (const float4*)&KV[d2 * 64 + eb];
        float4 v0 = kvp[0], v1 = kvp[1], v2 = kvp[2], v3 = kvp[3];
        acc[0]  = fmaf(qd, v0.x, acc[0]);  acc[1]  = fmaf(qd, v0.y, acc[1]);
        acc[2]  = fmaf(qd, v0.z, acc[2]);  acc[3]  = fmaf(qd, v0.w, acc[3]);
        acc[4]  = fmaf(qd, v1.x, acc[4]);  acc[5]  = fmaf(qd, v1.y, acc[5]);
        acc[6]  = fmaf(qd, v1.z, acc[6]);  acc[7]  = fmaf(qd, v1.w, acc[7]);
        acc[8]  = fmaf(qd, v2.x, acc[8]);  acc[9]  = fmaf(qd, v2.y, acc[9]);
        acc[10] = fmaf(qd, v2.z, acc[10]); acc[11] = fmaf(qd, v2.w, acc[11]);
        acc[12] = fmaf(qd, v3.x, acc[12]); acc[13] = fmaf(qd, v3.y, acc[13]);
        acc[14] = fmaf(qd, v3.z, acc[14]); acc[15] = fmaf(qd, v3.w, acc[15]);
    }

    float inv = 1.f / fmaxf(nrm, 1e-6f);
    const size_t idx = base + (size_t)(t0 + tl) * Dc + eb;
#pragma unroll
    for (int j = 0; j < 4; j++) {
        float a0 = acc[j * 4 + 0] * inv, a1 = acc[j * 4 + 1] * inv;
        float a2 = acc[j * 4 + 2] * inv, a3 = acc[j * 4 + 3] * inv;
        float h0 = __bfloat162float(__float2bfloat16(a0));
        float h1 = __bfloat162float(__float2bfloat16(a1));
        float h2 = __bfloat162float(__float2bfloat16(a2));
        float h3 = __bfloat162float(__float2bfloat16(a3));
        *(uint2*)(g_ah + idx + j * 4) = make_uint2(pack_bf2(a0, a1), pack_bf2(a2, a3));
        *(uint2*)(g_al + idx + j * 4) = make_uint2(pack_bf2(a0 - h0, a1 - h1),
                                                   pack_bf2(a2 - h2, a3 - h3));
    }
}

// ---------------------------------------------------------------------------
extern "C" void kernel_launch(void* const* d_in, const int* in_sizes, int n_in,
                              void* d_out, int out_size)
{
    const float* x          = (const float*)d_in[0];
    const unsigned char* mk = (const unsigned char*)d_in[1];
    float* out              = (float*)d_out;

    float *qp, *kp, *vp;
    unsigned char* mkc;
    __nv_bfloat16 *xh, *xl, *ah, *al, *wh, *wl;
    cudaGetSymbolAddress((void**)&qp, g_q);
    cudaGetSymbolAddress((void**)&kp, g_k);
    cudaGetSymbolAddress((void**)&vp, g_v);
    cudaGetSymbolAddress((void**)&mkc, g_mask);
    cudaGetSymbolAddress((void**)&xh, g_xh);
    cudaGetSymbolAddress((void**)&xl, g_xl);
    cudaGetSymbolAddress((void**)&ah, g_ah);
    cudaGetSymbolAddress((void**)&al, g_al);
    cudaGetSymbolAddress((void**)&wh, g_wh);
    cudaGetSymbolAddress((void**)&wl, g_wl);

    cudaFuncSetAttribute(gemm_tc_kernel,
                         cudaFuncAttributeMaxDynamicSharedMemorySize, GSM_TOTAL);

    // Launch order chosen so ncu (-s 5 -c 1) profiles a GEMM (6th launch).
    split_kernel<<<4096, 256>>>((const float4*)x, (uint2*)xh, (uint2*)xl, BT * Dc / 4);      // 1
    splitw_kernel<<<dim3(512, 4), 256>>>((const float4*)d_in[2], (const float4*)d_in[3],
                                         (const float4*)d_in[4], (const float4*)d_in[5]);    // 2
    mask_convert_kernel<<<64, 256>>>(mk);                                                    // 3

    dim3 ggrid(Dc / 128, BT / 128);   // (8, 128)
    gemm_tc_kernel<<<ggrid, 256, GSM_TOTAL>>>(xh, xl, wh + 0 * (size_t)Dc * Dc, wl + 0 * (size_t)Dc * Dc, qp, mkc, 1);  // 4
    gemm_tc_kernel<<<ggrid, 256, GSM_TOTAL>>>(xh, xl, wh + 1 * (size_t)Dc * Dc, wl + 1 * (size_t)Dc * Dc, kp, mkc, 2);  // 5
    gemm_tc_kernel<<<ggrid, 256, GSM_TOTAL>>>(xh, xl, wh + 2 * (size_t)Dc * Dc, wl + 2 * (size_t)Dc * Dc, vp, mkc, 3);  // 6 <- profiled
    kv_partial_kernel<<<dim3(BH, SPLIT), 256>>>();
    kv_reduce_kernel<<<BH, 256>>>();
    attn_out_kernel<<<dim3(Tc / 64, BH), 256>>>();
    gemm_tc_kernel<<<ggrid, 256, GSM_TOTAL>>>(ah, al, wh + 3 * (size_t)Dc * Dc, wl + 3 * (size_t)Dc * Dc, out, mkc, 0);
}